// round 11
// baseline (speedup 1.0000x reference)
#include <cuda_runtime.h>
#include <cstdint>
#include <math.h>

// ---------------------------------------------------------------------------
// TSI_Encoder, round 11: pre-split hi/lo operands + cp.async-only producers.
//   - Weights pre-split once (prep kernel); featgen writes Fhi/Flo; GEMM
//     epilogues write Hhi/Hlo. Hot loop: 12 cp.async.cg per thread, no split
//     math, no register round-trip, no LDG array traffic.
//   - 3xTF32 cg1 SS-mode MMA skeleton unchanged (verified rel_err 1.1e-5).
// ---------------------------------------------------------------------------

#define EPSF 1e-5f
#define M_TOTAL 147456   // 1024 * 144

#if defined(__CUDA_ARCH_FEAT_SM103_ALL) || defined(__CUDA_ARCH_FEAT_SM101_ALL) || \
    defined(__CUDA_ARCH_FEAT_SM100_ALL) ||                                        \
    (defined(__CUDA_ARCH_SPECIFIC__) && (__CUDA_ARCH_SPECIFIC__ >= 1000)) ||      \
    (defined(__CUDA_ARCH_FAMILY_SPECIFIC__) && (__CUDA_ARCH_FAMILY_SPECIFIC__ >= 1000))
#define HAS_TCGEN05 1
#else
#define HAS_TCGEN05 0
#endif

// split activations / features (hi, lo) + plain final layer
__device__ float g_Fhi [147456ULL * 588];
__device__ float g_Flo [147456ULL * 588];
__device__ float g_H0hi[147456ULL * 512];
__device__ float g_H0lo[147456ULL * 512];
__device__ float g_H1hi[147456ULL * 384];
__device__ float g_H1lo[147456ULL * 384];
__device__ float g_H2  [147456ULL * 256];
// split weights
__device__ float g_W0hi[512 * 588], g_W0lo[512 * 588];
__device__ float g_W1hi[384 * 512], g_W1lo[384 * 512];
__device__ float g_W2hi[256 * 384], g_W2lo[256 * 384];
// zero source for K-tail cp.async redirection
__device__ float g_zero16[4] = {0.f, 0.f, 0.f, 0.f};

// ======================== inline PTX helpers ========================
#if HAS_TCGEN05
__device__ __forceinline__ uint32_t elect_one() {
    uint32_t pred;
    asm volatile("{\n\t.reg .pred p;\n\telect.sync _|p, 0xFFFFFFFF;\n\tselp.b32 %0, 1, 0, p;\n\t}"
                 : "=r"(pred));
    return pred;
}
__device__ __forceinline__ void mbar_init(uint32_t addr, uint32_t cnt) {
    asm volatile("mbarrier.init.shared.b64 [%0], %1;" :: "r"(addr), "r"(cnt) : "memory");
}
__device__ __forceinline__ void mbar_wait(uint32_t mbar, uint32_t parity) {
    asm volatile(
        "{\n\t.reg .pred P1;\n\t"
        "WAIT_LOOP_%=:\n\t"
        "mbarrier.try_wait.parity.acquire.cta.shared::cta.b64 P1, [%0], %1, 0x989680;\n\t"
        "@P1 bra.uni WAIT_DONE_%=;\n\t"
        "bra.uni WAIT_LOOP_%=;\n\t"
        "WAIT_DONE_%=:\n\t}"
        :: "r"(mbar), "r"(parity) : "memory");
}
__device__ __forceinline__ void tmem_alloc(uint32_t dst_smem, uint32_t ncols) {
    asm volatile("tcgen05.alloc.cta_group::1.sync.aligned.shared::cta.b32 [%0], %1;"
                 :: "r"(dst_smem), "r"(ncols) : "memory");
}
__device__ __forceinline__ void tmem_relinquish() {
    asm volatile("tcgen05.relinquish_alloc_permit.cta_group::1.sync.aligned;");
}
__device__ __forceinline__ void tmem_dealloc(uint32_t tmem, uint32_t ncols) {
    asm volatile("tcgen05.dealloc.cta_group::1.sync.aligned.b32 %0, %1;" :: "r"(tmem), "r"(ncols));
}
__device__ __forceinline__ void tc_commit(uint32_t mbar) {
    asm volatile("tcgen05.commit.cta_group::1.mbarrier::arrive::one.shared::cluster.b64 [%0];"
                 :: "r"(mbar) : "memory");
}
__device__ __forceinline__ void tc_fence_after() {
    asm volatile("tcgen05.fence::after_thread_sync;" ::: "memory");
}
__device__ __forceinline__ void tc_fence_before() {
    asm volatile("tcgen05.fence::before_thread_sync;" ::: "memory");
}
__device__ __forceinline__ void tc_wait_ld() {
    asm volatile("tcgen05.wait::ld.sync.aligned;" ::: "memory");
}
__device__ __forceinline__ void cp16(uint32_t dst, const void* src) {
    asm volatile("cp.async.cg.shared.global [%0], [%1], 16;" :: "r"(dst), "l"(src) : "memory");
}
#define CP_COMMIT() asm volatile("cp.async.commit_group;" ::: "memory")
#define CP_WAIT0()  asm volatile("cp.async.wait_group 0;" ::: "memory")
#define LDTM_X32(r, a) \
    asm volatile( \
        "tcgen05.ld.sync.aligned.32x32b.x32.b32 " \
        "{%0, %1, %2, %3, %4, %5, %6, %7, " \
        " %8, %9, %10, %11, %12, %13, %14, %15, " \
        " %16, %17, %18, %19, %20, %21, %22, %23, " \
        " %24, %25, %26, %27, %28, %29, %30, %31}, [%32];" \
        : "=r"((r)[0]),  "=r"((r)[1]),  "=r"((r)[2]),  "=r"((r)[3]), \
          "=r"((r)[4]),  "=r"((r)[5]),  "=r"((r)[6]),  "=r"((r)[7]), \
          "=r"((r)[8]),  "=r"((r)[9]),  "=r"((r)[10]), "=r"((r)[11]), \
          "=r"((r)[12]), "=r"((r)[13]), "=r"((r)[14]), "=r"((r)[15]), \
          "=r"((r)[16]), "=r"((r)[17]), "=r"((r)[18]), "=r"((r)[19]), \
          "=r"((r)[20]), "=r"((r)[21]), "=r"((r)[22]), "=r"((r)[23]), \
          "=r"((r)[24]), "=r"((r)[25]), "=r"((r)[26]), "=r"((r)[27]), \
          "=r"((r)[28]), "=r"((r)[29]), "=r"((r)[30]), "=r"((r)[31]) \
        : "r"(a))

// tf32 SS-mode MMA: D[tmem] (+)= A(smem desc) * B(smem desc)^T, K=8 per call.
__device__ __forceinline__ void mma_tf32_ss(uint32_t d, uint64_t a_desc, uint64_t b_desc,
                                            uint32_t idesc, uint32_t en) {
    asm volatile(
        "{\n\t.reg .pred p;\n\t"
        "setp.ne.u32 p, %5, 0;\n\t"
        "tcgen05.mma.cta_group::1.kind::tf32 [%0], %1, %2, %3, {%4, %4, %4, %4}, p;\n\t"
        "}"
        :: "r"(d), "l"(a_desc), "l"(b_desc), "r"(idesc), "r"(0u), "r"(en)
        : "memory");
}
#endif  // HAS_TCGEN05

__device__ __forceinline__ uint32_t smem_u32(const void* p) {
    uint32_t a;
    asm("{ .reg .u64 t; cvta.to.shared.u64 t, %1; cvt.u32.u64 %0, t; }" : "=r"(a) : "l"(p));
    return a;
}
__device__ __forceinline__ uint32_t sw128(uint32_t off) {
    return off ^ ((off >> 3) & 0x70);
}

// SW128 K-major smem descriptor base: layout=SW128(2), version=1, SBO=64, LBO=1
static constexpr uint64_t DESC_BASE_SW128 =
    (uint64_t(2) << 61) | (uint64_t(1) << 46) | (uint64_t(64) << 32) | (uint64_t(1) << 16);
__device__ __forceinline__ uint64_t make_desc(uint32_t addr) {
    return DESC_BASE_SW128 | ((uint64_t)(addr >> 4) & 0x3FFF);
}

// idesc kind::tf32, D=F32, A=B=TF32 K-major, M=128
__device__ __forceinline__ constexpr uint32_t idesc_tf32(int n) {
    return (1u << 4) | (2u << 7) | (2u << 10) | ((uint32_t)(n / 8) << 17) | (8u << 24);
}

// Mask split: hi keeps tf32-representable top bits exactly; lo = x - hi (exact FADD).
__device__ __forceinline__ float hi_part(float x) {
    return __uint_as_float(__float_as_uint(x) & 0xFFFFE000u);
}

// ---------------------------------------------------------------------------
// Weight pre-split: w -> (hi, lo). Tiny; runs once per launch.
// ---------------------------------------------------------------------------
__global__ __launch_bounds__(256) void split_kernel(const float* __restrict__ src,
                                                    float* __restrict__ hi,
                                                    float* __restrict__ lo, int n)
{
    int i = blockIdx.x * 256 + threadIdx.x;
    if (i < n) {
        float x = src[i];
        float h = hi_part(x);
        hi[i] = h;
        lo[i] = x - h;
    }
}

// ---------------------------------------------------------------------------
// Feature generation, now writing split features (hi/lo exact decomposition).
// ---------------------------------------------------------------------------
__global__ __launch_bounds__(224) void featgen_kernel(const float* __restrict__ x) {
    int m = blockIdx.x;
    int b = m / 144;
    int p = m - b * 144;
    int h = p / 12;
    int w = p - h * 12;

    __shared__ float sx[168];
    int tid = threadIdx.x;
    if (tid < 168) sx[tid] = (tid == 167) ? 0.f : __ldg(&x[b * 168 + tid]);
    __syncthreads();

    if (tid < 196) {
        int i1 = tid / 14;
        int j1 = tid - i1 * 14;
        float xi = sx[i1 * 12 + h];
        float xj = sx[j1 * 12 + w];
        float d  = xj - xi;
        float r  = __frcp_rn(xi + xj + EPSF);
        float v0 = d, v1 = d * r, v2 = xj * r;
        size_t o = (size_t)m * 588 + tid * 3;
        float h0 = hi_part(v0), h1 = hi_part(v1), h2 = hi_part(v2);
        g_Fhi[o + 0] = h0; g_Flo[o + 0] = v0 - h0;
        g_Fhi[o + 1] = h1; g_Flo[o + 1] = v1 - h1;
        g_Fhi[o + 2] = h2; g_Flo[o + 2] = v2 - h2;
    }
}

// ---------------------------------------------------------------------------
// GEMM + bias + ReLU with pre-split operands.
//   C[m, n0+j] = relu( sum_k (Ahi+Alo)[m,k] * (Whi+Wlo)[n0+j,k] + bias )
// CTA tile 128 x NT; K chunks of 32; double-buffered stages (Ahi|Alo|Bhi|Blo);
// producers: pure cp.async.cg (12 per thread); MMA: 3 products per kk.
// SPLIT_OUT: epilogue writes (Chi, Clo); else plain C into Chi.
// ---------------------------------------------------------------------------
template<int NT, int N, int K, bool SPLIT_OUT>
__global__ __launch_bounds__(512)
void gemm_tc_kernel(const float* __restrict__ Ahi, const float* __restrict__ Alo,
                    const float* __restrict__ Bhi_g, const float* __restrict__ Blo_g,
                    const float* __restrict__ bias,
                    float* __restrict__ Chi, float* __restrict__ Clo)
{
    extern __shared__ char smem[];
#if HAS_TCGEN05
    static_assert(NT % 64 == 0 && NT <= 256 && N % NT == 0 && K % 4 == 0, "tile assumptions");
    constexpr int BK  = 32;
    constexpr int T   = (K + BK - 1) / BK;
    constexpr int TAILV = (K % BK) / 4;          // valid float4 slots in tail chunk (0 = none)
    constexpr int SLB = NT * 8 / 512;            // B 16B-chunks per thread per half
    constexpr int AHI = 0, ALO = 16384, BHI = 32768;
    constexpr int BLO   = BHI + NT * 128;
    constexpr int STAGE = 32768 + 2 * NT * 128;
    constexpr int TILE0 = 1024;
    constexpr uint32_t ID = idesc_tf32(NT);

    const uint32_t sbase = smem_u32(smem);
    const int tid = threadIdx.x;
    const int wid = tid >> 5, lid = tid & 31;
    const int m0 = blockIdx.x * 128;
    const int n0 = blockIdx.y * NT;

    if (wid == 0) {
        tmem_alloc(sbase, 512);
        tmem_relinquish();
    }
    if (tid == 0) { mbar_init(sbase + 8, 1); mbar_init(sbase + 16, 1); }
    __syncthreads();
    uint32_t tmem;
    asm volatile("ld.shared.b32 %0, [%1];" : "=r"(tmem) : "r"(sbase));

    const float* zsrc = g_zero16;
    const ptrdiff_t dA = Alo - Ahi;              // hi->lo pointer delta (elements)
    const ptrdiff_t dB = Blo_g - Bhi_g;

    // ---- per-thread slot geometry (k-invariant) ----
    const float* aSrc[2];
    uint32_t offA[2];
    int c4A[2];
#pragma unroll
    for (int p = 0; p < 2; ++p) {
        int slot = tid + p * 512;                // 1024 A 16B-chunks per half
        int row  = slot >> 3;
        int c4   = slot & 7;
        aSrc[p]  = &Ahi[(size_t)(m0 + row) * K + c4 * 4];
        offA[p]  = sw128(row * 128 + c4 * 16);
        c4A[p]   = c4;
    }
    const float* bSrc[SLB];
    uint32_t offB[SLB];
    int c4B[SLB];
#pragma unroll
    for (int p = 0; p < SLB; ++p) {
        int slot = tid + p * 512;                // NT*8 B 16B-chunks per half
        int row  = slot >> 3;
        int c4   = slot & 7;
        bSrc[p]  = &Bhi_g[(size_t)(n0 + row) * K + c4 * 4];
        offB[p]  = sw128(row * 128 + c4 * 16);
        c4B[p]   = c4;
    }

#pragma unroll 1
    for (int t = 0; t < T; ++t) {
        const int buf = t & 1;
        const uint32_t stage = sbase + TILE0 + buf * STAGE;
        if (t >= 2) mbar_wait(sbase + 8 + 8 * buf, ((t - 2) >> 1) & 1);

        const bool tail = (TAILV > 0) && (t == T - 1);
        const int koff = t * BK;
        // ---- A: 4 cp.asyncs ----
#pragma unroll
        for (int p = 0; p < 2; ++p) {
            bool ok = !tail || (c4A[p] < TAILV);
            const float* sh = ok ? (aSrc[p] + koff) : zsrc;
            const float* sl = ok ? (aSrc[p] + koff + dA) : zsrc;
            cp16(stage + AHI + offA[p], sh);
            cp16(stage + ALO + offA[p], sl);
        }
        // ---- B: 2*SLB cp.asyncs ----
#pragma unroll
        for (int p = 0; p < SLB; ++p) {
            bool ok = !tail || (c4B[p] < TAILV);
            const float* sh = ok ? (bSrc[p] + koff) : zsrc;
            const float* sl = ok ? (bSrc[p] + koff + dB) : zsrc;
            cp16(stage + BHI + offB[p], sh);
            cp16(stage + BLO + offB[p], sl);
        }
        CP_COMMIT();
        CP_WAIT0();
        asm volatile("fence.proxy.async.shared::cta;" ::: "memory");
        __syncthreads();

        if (wid == 0 && elect_one()) {
            uint64_t dAhi = make_desc(stage + AHI);
            uint64_t dAlo = make_desc(stage + ALO);
            uint64_t dBhi = make_desc(stage + BHI);
            uint64_t dBlo = make_desc(stage + BLO);
#pragma unroll
            for (int kk = 0; kk < 4; ++kk) {
                uint32_t en0 = (t > 0 || kk > 0) ? 1u : 0u;
                mma_tf32_ss(tmem, dAhi + kk * 2, dBhi + kk * 2, ID, en0);
                mma_tf32_ss(tmem, dAhi + kk * 2, dBlo + kk * 2, ID, 1u);
                mma_tf32_ss(tmem, dAlo + kk * 2, dBhi + kk * 2, ID, 1u);
            }
            tc_commit(sbase + 8 + 8 * buf);
        }
    }

    // Wait for the last commit (tensor pipe is in-order), then read D.
    mbar_wait(sbase + 8 + 8 * ((T - 1) & 1), ((T - 1) >> 1) & 1);
    tc_fence_after();

    // epilogue: warps 0-7; warp w = subpartition w&3, col half w>>2
    if (wid < 8) {
        const int m = m0 + (wid & 3) * 32 + lid;
        const int ch0 = (wid >> 2) * (NT / 2);
        float* crow = &Chi[(size_t)m * N + n0];
        float* lrow = SPLIT_OUT ? &Clo[(size_t)m * N + n0] : nullptr;
#pragma unroll
        for (int c0 = ch0; c0 < ch0 + NT / 2; c0 += 32) {
            uint32_t r[32];
            LDTM_X32(r, tmem + c0);
            tc_wait_ld();
#pragma unroll
            for (int j = 0; j < 32; j += 4) {
                float4 v;
                v.x = fmaxf(__uint_as_float(r[j + 0]) + __ldg(&bias[n0 + c0 + j + 0]), 0.f);
                v.y = fmaxf(__uint_as_float(r[j + 1]) + __ldg(&bias[n0 + c0 + j + 1]), 0.f);
                v.z = fmaxf(__uint_as_float(r[j + 2]) + __ldg(&bias[n0 + c0 + j + 2]), 0.f);
                v.w = fmaxf(__uint_as_float(r[j + 3]) + __ldg(&bias[n0 + c0 + j + 3]), 0.f);
                if (SPLIT_OUT) {
                    float4 hh, ll;
                    hh.x = hi_part(v.x); ll.x = v.x - hh.x;
                    hh.y = hi_part(v.y); ll.y = v.y - hh.y;
                    hh.z = hi_part(v.z); ll.z = v.z - hh.z;
                    hh.w = hi_part(v.w); ll.w = v.w - hh.w;
                    *reinterpret_cast<float4*>(crow + c0 + j) = hh;
                    *reinterpret_cast<float4*>(lrow + c0 + j) = ll;
                } else {
                    *reinterpret_cast<float4*>(crow + c0 + j) = v;
                }
            }
        }
        tc_fence_before();
    }
    __syncthreads();
    if (wid == 0) tmem_dealloc(tmem, 512);

#else  // ---------------- SIMT fp32 fallback (plain sm_103 cubin) ----------
    float (*As)[130] = reinterpret_cast<float (*)[130]>(smem);               // [16][130]
    float (*Bs)[66]  = reinterpret_cast<float (*)[66]>(smem + 16 * 130 * 4); // [16][66]

    const int tid = threadIdx.x;
    const int m0 = blockIdx.x * 128;
    const int nbase = blockIdx.y * NT;
    const int tx = tid & 15;
    const int ty = (tid & 255) >> 4;
    const int ntiles = (K + 15) / 16;

    for (int n0 = nbase; n0 < nbase + NT; n0 += 64) {
        float acc[8][4];
#pragma unroll
        for (int i = 0; i < 8; ++i)
#pragma unroll
            for (int j = 0; j < 4; ++j) acc[i][j] = 0.f;

        for (int t = 0; t < ntiles; ++t) {
            int k0 = t * 16;
            {   // A tile: 512 float4 slots, one per thread (hi+lo recombined)
                int idx = tid;
                int ml  = idx >> 2;
                int kl  = (idx & 3) * 4;
                int gk  = k0 + kl;
                float4 v = make_float4(0.f, 0.f, 0.f, 0.f);
                if (gk < K) {
                    size_t o = (size_t)(m0 + ml) * K + gk;
                    float4 h = *reinterpret_cast<const float4*>(&Ahi[o]);
                    float4 l = *reinterpret_cast<const float4*>(&Alo[o]);
                    v.x = h.x + l.x; v.y = h.y + l.y; v.z = h.z + l.z; v.w = h.w + l.w;
                }
                As[kl + 0][ml] = v.x; As[kl + 1][ml] = v.y;
                As[kl + 2][ml] = v.z; As[kl + 3][ml] = v.w;
            }
            if (tid < 256) {  // B tile: 256 slots (hi+lo recombined)
                int idx = tid;
                int nl  = idx >> 2;
                int kl  = (idx & 3) * 4;
                int gk  = k0 + kl;
                float4 v = make_float4(0.f, 0.f, 0.f, 0.f);
                if (gk < K) {
                    size_t o = (size_t)(n0 + nl) * K + gk;
                    float4 h = *reinterpret_cast<const float4*>(&Bhi_g[o]);
                    float4 l = *reinterpret_cast<const float4*>(&Blo_g[o]);
                    v.x = h.x + l.x; v.y = h.y + l.y; v.z = h.z + l.z; v.w = h.w + l.w;
                }
                Bs[kl + 0][nl] = v.x; Bs[kl + 1][nl] = v.y;
                Bs[kl + 2][nl] = v.z; Bs[kl + 3][nl] = v.w;
            }
            __syncthreads();
            if (tid < 256) {
#pragma unroll
                for (int kk = 0; kk < 16; ++kk) {
                    float a[8], bb[4];
#pragma unroll
                    for (int i = 0; i < 8; ++i) a[i] = As[kk][ty * 8 + i];
#pragma unroll
                    for (int j = 0; j < 4; ++j) bb[j] = Bs[kk][tx * 4 + j];
#pragma unroll
                    for (int i = 0; i < 8; ++i)
#pragma unroll
                        for (int j = 0; j < 4; ++j)
                            acc[i][j] = fmaf(a[i], bb[j], acc[i][j]);
                }
            }
            __syncthreads();
        }

        if (tid < 256) {
#pragma unroll
            for (int i = 0; i < 8; ++i) {
                int m = m0 + ty * 8 + i;
                int n = n0 + tx * 4;
#pragma unroll
                for (int j = 0; j < 4; ++j) {
                    float v = fmaxf(acc[i][j] + bias[n + j], 0.f);
                    if (SPLIT_OUT) {
                        float h = hi_part(v);
                        Chi[(size_t)m * N + n + j] = h;
                        Clo[(size_t)m * N + n + j] = v - h;
                    } else {
                        Chi[(size_t)m * N + n + j] = v;
                    }
                }
            }
        }
        __syncthreads();
    }
#endif
}

// ---------------------------------------------------------------------------
// Final reduction (unchanged; reads plain H2).
// ---------------------------------------------------------------------------
__global__ __launch_bounds__(256) void reduce_kernel(
    const float* __restrict__ wm_in, float* __restrict__ out)
{
    __shared__ float wms[16 * 144];
    __shared__ float rsum[16];
    int b = blockIdx.x;
    int tid = threadIdx.x;

    for (int i = tid; i < 16 * 144; i += 256)
        wms[i] = expf(wm_in[i]);
    __syncthreads();
    if (tid < 16) {
        float s = 0.f;
        for (int p = 0; p < 144; ++p) s += wms[tid * 144 + p];
        rsum[tid] = 1.f / s;
    }
    __syncthreads();

    int g = tid >> 4;
    const float* h2 = g_H2 + (size_t)b * 144 * 256;
    float acc = 0.f;
    for (int p = 0; p < 144; ++p)
        acc = fmaf(h2[p * 256 + tid], wms[g * 144 + p], acc);
    acc *= rsum[g];
    out[b * 256 + tid] = fmaxf(acc, 0.f);
}

// ---------------------------------------------------------------------------
extern "C" void kernel_launch(void* const* d_in, const int* in_sizes, int n_in,
                              void* d_out, int out_size)
{
    const float* x  = (const float*)d_in[0];
    const float* w0 = (const float*)d_in[1];
    const float* b0 = (const float*)d_in[2];
    const float* w1 = (const float*)d_in[3];
    const float* b1 = (const float*)d_in[4];
    const float* w2 = (const float*)d_in[5];
    const float* b2 = (const float*)d_in[6];
    const float* wm = (const float*)d_in[7];
    float* out = (float*)d_out;

    float *Fhi, *Flo, *H0hi, *H0lo, *H1hi, *H1lo, *H2;
    float *W0hi, *W0lo, *W1hi, *W1lo, *W2hi, *W2lo;
    cudaGetSymbolAddress((void**)&Fhi,  g_Fhi);
    cudaGetSymbolAddress((void**)&Flo,  g_Flo);
    cudaGetSymbolAddress((void**)&H0hi, g_H0hi);
    cudaGetSymbolAddress((void**)&H0lo, g_H0lo);
    cudaGetSymbolAddress((void**)&H1hi, g_H1hi);
    cudaGetSymbolAddress((void**)&H1lo, g_H1lo);
    cudaGetSymbolAddress((void**)&H2,   g_H2);
    cudaGetSymbolAddress((void**)&W0hi, g_W0hi);
    cudaGetSymbolAddress((void**)&W0lo, g_W0lo);
    cudaGetSymbolAddress((void**)&W1hi, g_W1hi);
    cudaGetSymbolAddress((void**)&W1lo, g_W1lo);
    cudaGetSymbolAddress((void**)&W2hi, g_W2hi);
    cudaGetSymbolAddress((void**)&W2lo, g_W2lo);

    // SMEM: ctrl 1024 + 2 stages * (32768 + 2*NT*128)
    constexpr int S0 = 1024 + 2 * (32768 + 2 * 256 * 128);  // 197632 (NT=256)
    constexpr int S1 = 1024 + 2 * (32768 + 2 * 192 * 128);  // 164864 (NT=192)
    constexpr int S2 = 1024 + 2 * (32768 + 2 * 256 * 128);  // 197632 (NT=256)
    cudaFuncSetAttribute(gemm_tc_kernel<256, 512, 588, true >, cudaFuncAttributeMaxDynamicSharedMemorySize, S0);
    cudaFuncSetAttribute(gemm_tc_kernel<192, 384, 512, true >, cudaFuncAttributeMaxDynamicSharedMemorySize, S1);
    cudaFuncSetAttribute(gemm_tc_kernel<256, 256, 384, false>, cudaFuncAttributeMaxDynamicSharedMemorySize, S2);

    // weight pre-split (cheap, graph-capturable)
    split_kernel<<<(512 * 588 + 255) / 256, 256>>>(w0, W0hi, W0lo, 512 * 588);
    split_kernel<<<(384 * 512 + 255) / 256, 256>>>(w1, W1hi, W1lo, 384 * 512);
    split_kernel<<<(256 * 384 + 255) / 256, 256>>>(w2, W2hi, W2lo, 256 * 384);

    featgen_kernel<<<M_TOTAL, 224>>>(x);

    gemm_tc_kernel<256, 512, 588, true ><<<dim3(M_TOTAL / 128, 2), 512, S0>>>(
        Fhi, Flo, W0hi, W0lo, b0, H0hi, H0lo);
    gemm_tc_kernel<192, 384, 512, true ><<<dim3(M_TOTAL / 128, 2), 512, S1>>>(
        H0hi, H0lo, W1hi, W1lo, b1, H1hi, H1lo);
    gemm_tc_kernel<256, 256, 384, false><<<dim3(M_TOTAL / 128, 1), 512, S2>>>(
        H1hi, H1lo, W2hi, W2lo, b2, H2, nullptr);

    reduce_kernel<<<1024, 256>>>(wm, out);
}

// round 12
// speedup vs baseline: 1.0333x; 1.0333x over previous
#include <cuda_runtime.h>
#include <cstdint>
#include <math.h>

// ---------------------------------------------------------------------------
// TSI_Encoder, round 12: R11 (pre-split hi/lo + cp.async producers) with the
// pipeline FIXED: distance-1 cp.async prefetch (issue chunk t+1, then
// wait_group 1 for chunk t) so global latency hides under MMA t.
// Numerics identical to R7/R10/R11 (rel_err 1.103664e-05).
// ---------------------------------------------------------------------------

#define EPSF 1e-5f
#define M_TOTAL 147456   // 1024 * 144

#if defined(__CUDA_ARCH_FEAT_SM103_ALL) || defined(__CUDA_ARCH_FEAT_SM101_ALL) || \
    defined(__CUDA_ARCH_FEAT_SM100_ALL) ||                                        \
    (defined(__CUDA_ARCH_SPECIFIC__) && (__CUDA_ARCH_SPECIFIC__ >= 1000)) ||      \
    (defined(__CUDA_ARCH_FAMILY_SPECIFIC__) && (__CUDA_ARCH_FAMILY_SPECIFIC__ >= 1000))
#define HAS_TCGEN05 1
#else
#define HAS_TCGEN05 0
#endif

// split activations / features (hi, lo) + plain final layer
__device__ float g_Fhi [147456ULL * 588];
__device__ float g_Flo [147456ULL * 588];
__device__ float g_H0hi[147456ULL * 512];
__device__ float g_H0lo[147456ULL * 512];
__device__ float g_H1hi[147456ULL * 384];
__device__ float g_H1lo[147456ULL * 384];
__device__ float g_H2  [147456ULL * 256];
// split weights
__device__ float g_W0hi[512 * 588], g_W0lo[512 * 588];
__device__ float g_W1hi[384 * 512], g_W1lo[384 * 512];
__device__ float g_W2hi[256 * 384], g_W2lo[256 * 384];
// zero source for K-tail cp.async redirection
__device__ float g_zero16[4] = {0.f, 0.f, 0.f, 0.f};

// ======================== inline PTX helpers ========================
#if HAS_TCGEN05
__device__ __forceinline__ uint32_t elect_one() {
    uint32_t pred;
    asm volatile("{\n\t.reg .pred p;\n\telect.sync _|p, 0xFFFFFFFF;\n\tselp.b32 %0, 1, 0, p;\n\t}"
                 : "=r"(pred));
    return pred;
}
__device__ __forceinline__ void mbar_init(uint32_t addr, uint32_t cnt) {
    asm volatile("mbarrier.init.shared.b64 [%0], %1;" :: "r"(addr), "r"(cnt) : "memory");
}
__device__ __forceinline__ void mbar_wait(uint32_t mbar, uint32_t parity) {
    asm volatile(
        "{\n\t.reg .pred P1;\n\t"
        "WAIT_LOOP_%=:\n\t"
        "mbarrier.try_wait.parity.acquire.cta.shared::cta.b64 P1, [%0], %1, 0x989680;\n\t"
        "@P1 bra.uni WAIT_DONE_%=;\n\t"
        "bra.uni WAIT_LOOP_%=;\n\t"
        "WAIT_DONE_%=:\n\t}"
        :: "r"(mbar), "r"(parity) : "memory");
}
__device__ __forceinline__ void tmem_alloc(uint32_t dst_smem, uint32_t ncols) {
    asm volatile("tcgen05.alloc.cta_group::1.sync.aligned.shared::cta.b32 [%0], %1;"
                 :: "r"(dst_smem), "r"(ncols) : "memory");
}
__device__ __forceinline__ void tmem_relinquish() {
    asm volatile("tcgen05.relinquish_alloc_permit.cta_group::1.sync.aligned;");
}
__device__ __forceinline__ void tmem_dealloc(uint32_t tmem, uint32_t ncols) {
    asm volatile("tcgen05.dealloc.cta_group::1.sync.aligned.b32 %0, %1;" :: "r"(tmem), "r"(ncols));
}
__device__ __forceinline__ void tc_commit(uint32_t mbar) {
    asm volatile("tcgen05.commit.cta_group::1.mbarrier::arrive::one.shared::cluster.b64 [%0];"
                 :: "r"(mbar) : "memory");
}
__device__ __forceinline__ void tc_fence_after() {
    asm volatile("tcgen05.fence::after_thread_sync;" ::: "memory");
}
__device__ __forceinline__ void tc_fence_before() {
    asm volatile("tcgen05.fence::before_thread_sync;" ::: "memory");
}
__device__ __forceinline__ void tc_wait_ld() {
    asm volatile("tcgen05.wait::ld.sync.aligned;" ::: "memory");
}
__device__ __forceinline__ void cp16(uint32_t dst, const void* src) {
    asm volatile("cp.async.cg.shared.global [%0], [%1], 16;" :: "r"(dst), "l"(src) : "memory");
}
#define CP_COMMIT() asm volatile("cp.async.commit_group;" ::: "memory")
#define CP_WAIT(n)  asm volatile("cp.async.wait_group %0;" :: "n"(n) : "memory")
#define LDTM_X32(r, a) \
    asm volatile( \
        "tcgen05.ld.sync.aligned.32x32b.x32.b32 " \
        "{%0, %1, %2, %3, %4, %5, %6, %7, " \
        " %8, %9, %10, %11, %12, %13, %14, %15, " \
        " %16, %17, %18, %19, %20, %21, %22, %23, " \
        " %24, %25, %26, %27, %28, %29, %30, %31}, [%32];" \
        : "=r"((r)[0]),  "=r"((r)[1]),  "=r"((r)[2]),  "=r"((r)[3]), \
          "=r"((r)[4]),  "=r"((r)[5]),  "=r"((r)[6]),  "=r"((r)[7]), \
          "=r"((r)[8]),  "=r"((r)[9]),  "=r"((r)[10]), "=r"((r)[11]), \
          "=r"((r)[12]), "=r"((r)[13]), "=r"((r)[14]), "=r"((r)[15]), \
          "=r"((r)[16]), "=r"((r)[17]), "=r"((r)[18]), "=r"((r)[19]), \
          "=r"((r)[20]), "=r"((r)[21]), "=r"((r)[22]), "=r"((r)[23]), \
          "=r"((r)[24]), "=r"((r)[25]), "=r"((r)[26]), "=r"((r)[27]), \
          "=r"((r)[28]), "=r"((r)[29]), "=r"((r)[30]), "=r"((r)[31]) \
        : "r"(a))

// tf32 SS-mode MMA: D[tmem] (+)= A(smem desc) * B(smem desc)^T, K=8 per call.
__device__ __forceinline__ void mma_tf32_ss(uint32_t d, uint64_t a_desc, uint64_t b_desc,
                                            uint32_t idesc, uint32_t en) {
    asm volatile(
        "{\n\t.reg .pred p;\n\t"
        "setp.ne.u32 p, %5, 0;\n\t"
        "tcgen05.mma.cta_group::1.kind::tf32 [%0], %1, %2, %3, {%4, %4, %4, %4}, p;\n\t"
        "}"
        :: "r"(d), "l"(a_desc), "l"(b_desc), "r"(idesc), "r"(0u), "r"(en)
        : "memory");
}
#endif  // HAS_TCGEN05

__device__ __forceinline__ uint32_t smem_u32(const void* p) {
    uint32_t a;
    asm("{ .reg .u64 t; cvta.to.shared.u64 t, %1; cvt.u32.u64 %0, t; }" : "=r"(a) : "l"(p));
    return a;
}
__device__ __forceinline__ uint32_t sw128(uint32_t off) {
    return off ^ ((off >> 3) & 0x70);
}

// SW128 K-major smem descriptor base: layout=SW128(2), version=1, SBO=64, LBO=1
static constexpr uint64_t DESC_BASE_SW128 =
    (uint64_t(2) << 61) | (uint64_t(1) << 46) | (uint64_t(64) << 32) | (uint64_t(1) << 16);
__device__ __forceinline__ uint64_t make_desc(uint32_t addr) {
    return DESC_BASE_SW128 | ((uint64_t)(addr >> 4) & 0x3FFF);
}

// idesc kind::tf32, D=F32, A=B=TF32 K-major, M=128
__device__ __forceinline__ constexpr uint32_t idesc_tf32(int n) {
    return (1u << 4) | (2u << 7) | (2u << 10) | ((uint32_t)(n / 8) << 17) | (8u << 24);
}

// Mask split: hi keeps tf32-representable top bits exactly; lo = x - hi (exact FADD).
__device__ __forceinline__ float hi_part(float x) {
    return __uint_as_float(__float_as_uint(x) & 0xFFFFE000u);
}

// ---------------------------------------------------------------------------
// Weight pre-split: w -> (hi, lo). Tiny; runs once per launch.
// ---------------------------------------------------------------------------
__global__ __launch_bounds__(256) void split_kernel(const float* __restrict__ src,
                                                    float* __restrict__ hi,
                                                    float* __restrict__ lo, int n)
{
    int i = blockIdx.x * 256 + threadIdx.x;
    if (i < n) {
        float x = src[i];
        float h = hi_part(x);
        hi[i] = h;
        lo[i] = x - h;
    }
}

// ---------------------------------------------------------------------------
// Feature generation, writing split features (hi/lo exact decomposition).
// ---------------------------------------------------------------------------
__global__ __launch_bounds__(224) void featgen_kernel(const float* __restrict__ x) {
    int m = blockIdx.x;
    int b = m / 144;
    int p = m - b * 144;
    int h = p / 12;
    int w = p - h * 12;

    __shared__ float sx[168];
    int tid = threadIdx.x;
    if (tid < 168) sx[tid] = (tid == 167) ? 0.f : __ldg(&x[b * 168 + tid]);
    __syncthreads();

    if (tid < 196) {
        int i1 = tid / 14;
        int j1 = tid - i1 * 14;
        float xi = sx[i1 * 12 + h];
        float xj = sx[j1 * 12 + w];
        float d  = xj - xi;
        float r  = __frcp_rn(xi + xj + EPSF);
        float v0 = d, v1 = d * r, v2 = xj * r;
        size_t o = (size_t)m * 588 + tid * 3;
        float h0 = hi_part(v0), h1 = hi_part(v1), h2 = hi_part(v2);
        g_Fhi[o + 0] = h0; g_Flo[o + 0] = v0 - h0;
        g_Fhi[o + 1] = h1; g_Flo[o + 1] = v1 - h1;
        g_Fhi[o + 2] = h2; g_Flo[o + 2] = v2 - h2;
    }
}

// ---------------------------------------------------------------------------
// GEMM + bias + ReLU with pre-split operands, pipelined cp.async producers.
//   C[m, n0+j] = relu( sum_k (Ahi+Alo)[m,k] * (Whi+Wlo)[n0+j,k] + bias )
// CTA tile 128 x NT; K chunks of 32; double-buffered stages (Ahi|Alo|Bhi|Blo).
// Pipeline: chunk t+1's cp.async group is issued BEFORE wait_group(1) for
// chunk t, so global latency hides under chunk t's MMA.
// ---------------------------------------------------------------------------
template<int NT, int N, int K, bool SPLIT_OUT>
__global__ __launch_bounds__(512)
void gemm_tc_kernel(const float* __restrict__ Ahi, const float* __restrict__ Alo,
                    const float* __restrict__ Bhi_g, const float* __restrict__ Blo_g,
                    const float* __restrict__ bias,
                    float* __restrict__ Chi, float* __restrict__ Clo)
{
    extern __shared__ char smem[];
#if HAS_TCGEN05
    static_assert(NT % 64 == 0 && NT <= 256 && N % NT == 0 && K % 4 == 0, "tile assumptions");
    constexpr int BK  = 32;
    constexpr int T   = (K + BK - 1) / BK;
    constexpr int TAILV = (K % BK) / 4;          // valid float4 slots in tail chunk (0 = none)
    constexpr int SLB = NT * 8 / 512;            // B 16B-chunks per thread per half
    constexpr int AHI = 0, ALO = 16384, BHI = 32768;
    constexpr int BLO   = BHI + NT * 128;
    constexpr int STAGE = 32768 + 2 * NT * 128;
    constexpr int TILE0 = 1024;
    constexpr uint32_t ID = idesc_tf32(NT);

    const uint32_t sbase = smem_u32(smem);
    const int tid = threadIdx.x;
    const int wid = tid >> 5, lid = tid & 31;
    const int m0 = blockIdx.x * 128;
    const int n0 = blockIdx.y * NT;

    if (wid == 0) {
        tmem_alloc(sbase, 512);
        tmem_relinquish();
    }
    if (tid == 0) { mbar_init(sbase + 8, 1); mbar_init(sbase + 16, 1); }
    __syncthreads();
    uint32_t tmem;
    asm volatile("ld.shared.b32 %0, [%1];" : "=r"(tmem) : "r"(sbase));

    const float* zsrc = g_zero16;
    const ptrdiff_t dA = Alo - Ahi;              // hi->lo pointer delta (elements)
    const ptrdiff_t dB = Blo_g - Bhi_g;

    // ---- per-thread slot geometry (k-invariant) ----
    const float* aSrc[2];
    uint32_t offA[2];
    int c4A[2];
#pragma unroll
    for (int p = 0; p < 2; ++p) {
        int slot = tid + p * 512;                // 1024 A 16B-chunks per half
        int row  = slot >> 3;
        int c4   = slot & 7;
        aSrc[p]  = &Ahi[(size_t)(m0 + row) * K + c4 * 4];
        offA[p]  = sw128(row * 128 + c4 * 16);
        c4A[p]   = c4;
    }
    const float* bSrc[SLB];
    uint32_t offB[SLB];
    int c4B[SLB];
#pragma unroll
    for (int p = 0; p < SLB; ++p) {
        int slot = tid + p * 512;                // NT*8 B 16B-chunks per half
        int row  = slot >> 3;
        int c4   = slot & 7;
        bSrc[p]  = &Bhi_g[(size_t)(n0 + row) * K + c4 * 4];
        offB[p]  = sw128(row * 128 + c4 * 16);
        c4B[p]   = c4;
    }

    // issue all 12 cp.asyncs + commit for chunk c
    auto issue_chunk = [&](int c) {
        const uint32_t stage = sbase + TILE0 + (c & 1) * STAGE;
        const bool tail = (TAILV > 0) && (c == T - 1);
        const int koff = c * BK;
#pragma unroll
        for (int p = 0; p < 2; ++p) {
            bool ok = !tail || (c4A[p] < TAILV);
            cp16(stage + AHI + offA[p], ok ? (aSrc[p] + koff) : zsrc);
            cp16(stage + ALO + offA[p], ok ? (aSrc[p] + koff + dA) : zsrc);
        }
#pragma unroll
        for (int p = 0; p < SLB; ++p) {
            bool ok = !tail || (c4B[p] < TAILV);
            cp16(stage + BHI + offB[p], ok ? (bSrc[p] + koff) : zsrc);
            cp16(stage + BLO + offB[p], ok ? (bSrc[p] + koff + dB) : zsrc);
        }
        CP_COMMIT();
    };

    // prologue: chunk 0 in flight
    issue_chunk(0);

#pragma unroll 1
    for (int t = 0; t < T; ++t) {
        // issue chunk t+1 (other buffer) before waiting on chunk t
        if (t + 1 < T) {
            // buffer (t+1)&1 is free once MMA of chunk t-1 completed
            if (t >= 1) mbar_wait(sbase + 8 + 8 * ((t + 1) & 1), ((t - 1) >> 1) & 1);
            issue_chunk(t + 1);
            CP_WAIT(1);      // chunk t complete; t+1 still in flight
        } else {
            CP_WAIT(0);      // last chunk
        }
        asm volatile("fence.proxy.async.shared::cta;" ::: "memory");
        __syncthreads();

        if (wid == 0 && elect_one()) {
            const uint32_t stage = sbase + TILE0 + (t & 1) * STAGE;
            uint64_t dAhi = make_desc(stage + AHI);
            uint64_t dAlo = make_desc(stage + ALO);
            uint64_t dBhi = make_desc(stage + BHI);
            uint64_t dBlo = make_desc(stage + BLO);
#pragma unroll
            for (int kk = 0; kk < 4; ++kk) {
                uint32_t en0 = (t > 0 || kk > 0) ? 1u : 0u;
                mma_tf32_ss(tmem, dAhi + kk * 2, dBhi + kk * 2, ID, en0);
                mma_tf32_ss(tmem, dAhi + kk * 2, dBlo + kk * 2, ID, 1u);
                mma_tf32_ss(tmem, dAlo + kk * 2, dBhi + kk * 2, ID, 1u);
            }
            tc_commit(sbase + 8 + 8 * (t & 1));
        }
    }

    // Wait for the last commit (tensor pipe is in-order), then read D.
    mbar_wait(sbase + 8 + 8 * ((T - 1) & 1), ((T - 1) >> 1) & 1);
    tc_fence_after();

    // epilogue: warps 0-7; warp w = subpartition w&3, col half w>>2
    if (wid < 8) {
        const int m = m0 + (wid & 3) * 32 + lid;
        const int ch0 = (wid >> 2) * (NT / 2);
        float* crow = &Chi[(size_t)m * N + n0];
        float* lrow = SPLIT_OUT ? &Clo[(size_t)m * N + n0] : nullptr;
#pragma unroll
        for (int c0 = ch0; c0 < ch0 + NT / 2; c0 += 32) {
            uint32_t r[32];
            LDTM_X32(r, tmem + c0);
            tc_wait_ld();
#pragma unroll
            for (int j = 0; j < 32; j += 4) {
                float4 v;
                v.x = fmaxf(__uint_as_float(r[j + 0]) + __ldg(&bias[n0 + c0 + j + 0]), 0.f);
                v.y = fmaxf(__uint_as_float(r[j + 1]) + __ldg(&bias[n0 + c0 + j + 1]), 0.f);
                v.z = fmaxf(__uint_as_float(r[j + 2]) + __ldg(&bias[n0 + c0 + j + 2]), 0.f);
                v.w = fmaxf(__uint_as_float(r[j + 3]) + __ldg(&bias[n0 + c0 + j + 3]), 0.f);
                if (SPLIT_OUT) {
                    float4 hh, ll;
                    hh.x = hi_part(v.x); ll.x = v.x - hh.x;
                    hh.y = hi_part(v.y); ll.y = v.y - hh.y;
                    hh.z = hi_part(v.z); ll.z = v.z - hh.z;
                    hh.w = hi_part(v.w); ll.w = v.w - hh.w;
                    *reinterpret_cast<float4*>(crow + c0 + j) = hh;
                    *reinterpret_cast<float4*>(lrow + c0 + j) = ll;
                } else {
                    *reinterpret_cast<float4*>(crow + c0 + j) = v;
                }
            }
        }
        tc_fence_before();
    }
    __syncthreads();
    if (wid == 0) tmem_dealloc(tmem, 512);

#else  // ---------------- SIMT fp32 fallback (plain sm_103 cubin) ----------
    float (*As)[130] = reinterpret_cast<float (*)[130]>(smem);               // [16][130]
    float (*Bs)[66]  = reinterpret_cast<float (*)[66]>(smem + 16 * 130 * 4); // [16][66]

    const int tid = threadIdx.x;
    const int m0 = blockIdx.x * 128;
    const int nbase = blockIdx.y * NT;
    const int tx = tid & 15;
    const int ty = (tid & 255) >> 4;
    const int ntiles = (K + 15) / 16;

    for (int n0 = nbase; n0 < nbase + NT; n0 += 64) {
        float acc[8][4];
#pragma unroll
        for (int i = 0; i < 8; ++i)
#pragma unroll
            for (int j = 0; j < 4; ++j) acc[i][j] = 0.f;

        for (int t = 0; t < ntiles; ++t) {
            int k0 = t * 16;
            {   // A tile: 512 float4 slots, one per thread (hi+lo recombined)
                int idx = tid;
                int ml  = idx >> 2;
                int kl  = (idx & 3) * 4;
                int gk  = k0 + kl;
                float4 v = make_float4(0.f, 0.f, 0.f, 0.f);
                if (gk < K) {
                    size_t o = (size_t)(m0 + ml) * K + gk;
                    float4 h = *reinterpret_cast<const float4*>(&Ahi[o]);
                    float4 l = *reinterpret_cast<const float4*>(&Alo[o]);
                    v.x = h.x + l.x; v.y = h.y + l.y; v.z = h.z + l.z; v.w = h.w + l.w;
                }
                As[kl + 0][ml] = v.x; As[kl + 1][ml] = v.y;
                As[kl + 2][ml] = v.z; As[kl + 3][ml] = v.w;
            }
            if (tid < 256) {  // B tile: 256 slots (hi+lo recombined)
                int idx = tid;
                int nl  = idx >> 2;
                int kl  = (idx & 3) * 4;
                int gk  = k0 + kl;
                float4 v = make_float4(0.f, 0.f, 0.f, 0.f);
                if (gk < K) {
                    size_t o = (size_t)(n0 + nl) * K + gk;
                    float4 h = *reinterpret_cast<const float4*>(&Bhi_g[o]);
                    float4 l = *reinterpret_cast<const float4*>(&Blo_g[o]);
                    v.x = h.x + l.x; v.y = h.y + l.y; v.z = h.z + l.z; v.w = h.w + l.w;
                }
                Bs[kl + 0][nl] = v.x; Bs[kl + 1][nl] = v.y;
                Bs[kl + 2][nl] = v.z; Bs[kl + 3][nl] = v.w;
            }
            __syncthreads();
            if (tid < 256) {
#pragma unroll
                for (int kk = 0; kk < 16; ++kk) {
                    float a[8], bb[4];
#pragma unroll
                    for (int i = 0; i < 8; ++i) a[i] = As[kk][ty * 8 + i];
#pragma unroll
                    for (int j = 0; j < 4; ++j) bb[j] = Bs[kk][tx * 4 + j];
#pragma unroll
                    for (int i = 0; i < 8; ++i)
#pragma unroll
                        for (int j = 0; j < 4; ++j)
                            acc[i][j] = fmaf(a[i], bb[j], acc[i][j]);
                }
            }
            __syncthreads();
        }

        if (tid < 256) {
#pragma unroll
            for (int i = 0; i < 8; ++i) {
                int m = m0 + ty * 8 + i;
                int n = n0 + tx * 4;
#pragma unroll
                for (int j = 0; j < 4; ++j) {
                    float v = fmaxf(acc[i][j] + bias[n + j], 0.f);
                    if (SPLIT_OUT) {
                        float h = hi_part(v);
                        Chi[(size_t)m * N + n + j] = h;
                        Clo[(size_t)m * N + n + j] = v - h;
                    } else {
                        Chi[(size_t)m * N + n + j] = v;
                    }
                }
            }
        }
        __syncthreads();
    }
#endif
}

// ---------------------------------------------------------------------------
// Final reduction (unchanged; reads plain H2).
// ---------------------------------------------------------------------------
__global__ __launch_bounds__(256) void reduce_kernel(
    const float* __restrict__ wm_in, float* __restrict__ out)
{
    __shared__ float wms[16 * 144];
    __shared__ float rsum[16];
    int b = blockIdx.x;
    int tid = threadIdx.x;

    for (int i = tid; i < 16 * 144; i += 256)
        wms[i] = expf(wm_in[i]);
    __syncthreads();
    if (tid < 16) {
        float s = 0.f;
        for (int p = 0; p < 144; ++p) s += wms[tid * 144 + p];
        rsum[tid] = 1.f / s;
    }
    __syncthreads();

    int g = tid >> 4;
    const float* h2 = g_H2 + (size_t)b * 144 * 256;
    float acc = 0.f;
    for (int p = 0; p < 144; ++p)
        acc = fmaf(h2[p * 256 + tid], wms[g * 144 + p], acc);
    acc *= rsum[g];
    out[b * 256 + tid] = fmaxf(acc, 0.f);
}

// ---------------------------------------------------------------------------
extern "C" void kernel_launch(void* const* d_in, const int* in_sizes, int n_in,
                              void* d_out, int out_size)
{
    const float* x  = (const float*)d_in[0];
    const float* w0 = (const float*)d_in[1];
    const float* b0 = (const float*)d_in[2];
    const float* w1 = (const float*)d_in[3];
    const float* b1 = (const float*)d_in[4];
    const float* w2 = (const float*)d_in[5];
    const float* b2 = (const float*)d_in[6];
    const float* wm = (const float*)d_in[7];
    float* out = (float*)d_out;

    float *Fhi, *Flo, *H0hi, *H0lo, *H1hi, *H1lo, *H2;
    float *W0hi, *W0lo, *W1hi, *W1lo, *W2hi, *W2lo;
    cudaGetSymbolAddress((void**)&Fhi,  g_Fhi);
    cudaGetSymbolAddress((void**)&Flo,  g_Flo);
    cudaGetSymbolAddress((void**)&H0hi, g_H0hi);
    cudaGetSymbolAddress((void**)&H0lo, g_H0lo);
    cudaGetSymbolAddress((void**)&H1hi, g_H1hi);
    cudaGetSymbolAddress((void**)&H1lo, g_H1lo);
    cudaGetSymbolAddress((void**)&H2,   g_H2);
    cudaGetSymbolAddress((void**)&W0hi, g_W0hi);
    cudaGetSymbolAddress((void**)&W0lo, g_W0lo);
    cudaGetSymbolAddress((void**)&W1hi, g_W1hi);
    cudaGetSymbolAddress((void**)&W1lo, g_W1lo);
    cudaGetSymbolAddress((void**)&W2hi, g_W2hi);
    cudaGetSymbolAddress((void**)&W2lo, g_W2lo);

    // SMEM: ctrl 1024 + 2 stages * (32768 + 2*NT*128)
    constexpr int S0 = 1024 + 2 * (32768 + 2 * 256 * 128);  // 197632 (NT=256)
    constexpr int S1 = 1024 + 2 * (32768 + 2 * 192 * 128);  // 164864 (NT=192)
    constexpr int S2 = 1024 + 2 * (32768 + 2 * 256 * 128);  // 197632 (NT=256)
    cudaFuncSetAttribute(gemm_tc_kernel<256, 512, 588, true >, cudaFuncAttributeMaxDynamicSharedMemorySize, S0);
    cudaFuncSetAttribute(gemm_tc_kernel<192, 384, 512, true >, cudaFuncAttributeMaxDynamicSharedMemorySize, S1);
    cudaFuncSetAttribute(gemm_tc_kernel<256, 256, 384, false>, cudaFuncAttributeMaxDynamicSharedMemorySize, S2);

    // weight pre-split (cheap, graph-capturable)
    split_kernel<<<(512 * 588 + 255) / 256, 256>>>(w0, W0hi, W0lo, 512 * 588);
    split_kernel<<<(384 * 512 + 255) / 256, 256>>>(w1, W1hi, W1lo, 384 * 512);
    split_kernel<<<(256 * 384 + 255) / 256, 256>>>(w2, W2hi, W2lo, 256 * 384);

    featgen_kernel<<<M_TOTAL, 224>>>(x);

    gemm_tc_kernel<256, 512, 588, true ><<<dim3(M_TOTAL / 128, 2), 512, S0>>>(
        Fhi, Flo, W0hi, W0lo, b0, H0hi, H0lo);
    gemm_tc_kernel<192, 384, 512, true ><<<dim3(M_TOTAL / 128, 2), 512, S1>>>(
        H0hi, H0lo, W1hi, W1lo, b1, H1hi, H1lo);
    gemm_tc_kernel<256, 256, 384, false><<<dim3(M_TOTAL / 128, 1), 512, S2>>>(
        H1hi, H1lo, W2hi, W2lo, b2, H2, nullptr);

    reduce_kernel<<<1024, 256>>>(wm, out);
}

// round 15
// speedup vs baseline: 1.4913x; 1.4432x over previous
#include <cuda_runtime.h>
#include <cstdint>
#include <math.h>

// ---------------------------------------------------------------------------
// TSI_Encoder, round 13: R10 skeleton (cg1 SS 3xTF32, A via LDG+split+STS,
// 512 threads) with WEIGHTS pre-split in DRAM and fetched by cp.async.cg,
// issued one chunk ahead (after the end-of-iter MMA(t-1) wait).
// Activations stay UNSPLIT in DRAM (R11/R12's split-activation storage
// doubled the dominant DRAM stream and regressed 2.4x -> reverted).
// ---------------------------------------------------------------------------

#define EPSF 1e-5f
#define M_TOTAL 147456   // 1024 * 144

#if defined(__CUDA_ARCH_FEAT_SM103_ALL) || defined(__CUDA_ARCH_FEAT_SM101_ALL) || \
    defined(__CUDA_ARCH_FEAT_SM100_ALL) ||                                        \
    (defined(__CUDA_ARCH_SPECIFIC__) && (__CUDA_ARCH_SPECIFIC__ >= 1000)) ||      \
    (defined(__CUDA_ARCH_FAMILY_SPECIFIC__) && (__CUDA_ARCH_FAMILY_SPECIFIC__ >= 1000))
#define HAS_TCGEN05 1
#else
#define HAS_TCGEN05 0
#endif

// unsplit activations (single DRAM stream)
__device__ float g_F [147456ULL * 588];
__device__ float g_H0[147456ULL * 512];
__device__ float g_H1[147456ULL * 384];
__device__ float g_H2[147456ULL * 256];
// pre-split weights (tiny; reused by all CTAs)
__device__ float g_W0hi[512 * 588], g_W0lo[512 * 588];
__device__ float g_W1hi[384 * 512], g_W1lo[384 * 512];
__device__ float g_W2hi[256 * 384], g_W2lo[256 * 384];
// zero source for K-tail cp.async redirection
__device__ float g_zero16[4] = {0.f, 0.f, 0.f, 0.f};

// ======================== inline PTX helpers ========================
#if HAS_TCGEN05
__device__ __forceinline__ uint32_t elect_one() {
    uint32_t pred;
    asm volatile("{\n\t.reg .pred p;\n\telect.sync _|p, 0xFFFFFFFF;\n\tselp.b32 %0, 1, 0, p;\n\t}"
                 : "=r"(pred));
    return pred;
}
__device__ __forceinline__ void mbar_init(uint32_t addr, uint32_t cnt) {
    asm volatile("mbarrier.init.shared.b64 [%0], %1;" :: "r"(addr), "r"(cnt) : "memory");
}
__device__ __forceinline__ void mbar_wait(uint32_t mbar, uint32_t parity) {
    asm volatile(
        "{\n\t.reg .pred P1;\n\t"
        "WAIT_LOOP_%=:\n\t"
        "mbarrier.try_wait.parity.acquire.cta.shared::cta.b64 P1, [%0], %1, 0x989680;\n\t"
        "@P1 bra.uni WAIT_DONE_%=;\n\t"
        "bra.uni WAIT_LOOP_%=;\n\t"
        "WAIT_DONE_%=:\n\t}"
        :: "r"(mbar), "r"(parity) : "memory");
}
__device__ __forceinline__ void tmem_alloc(uint32_t dst_smem, uint32_t ncols) {
    asm volatile("tcgen05.alloc.cta_group::1.sync.aligned.shared::cta.b32 [%0], %1;"
                 :: "r"(dst_smem), "r"(ncols) : "memory");
}
__device__ __forceinline__ void tmem_relinquish() {
    asm volatile("tcgen05.relinquish_alloc_permit.cta_group::1.sync.aligned;");
}
__device__ __forceinline__ void tmem_dealloc(uint32_t tmem, uint32_t ncols) {
    asm volatile("tcgen05.dealloc.cta_group::1.sync.aligned.b32 %0, %1;" :: "r"(tmem), "r"(ncols));
}
__device__ __forceinline__ void tc_commit(uint32_t mbar) {
    asm volatile("tcgen05.commit.cta_group::1.mbarrier::arrive::one.shared::cluster.b64 [%0];"
                 :: "r"(mbar) : "memory");
}
__device__ __forceinline__ void tc_fence_after() {
    asm volatile("tcgen05.fence::after_thread_sync;" ::: "memory");
}
__device__ __forceinline__ void tc_fence_before() {
    asm volatile("tcgen05.fence::before_thread_sync;" ::: "memory");
}
__device__ __forceinline__ void tc_wait_ld() {
    asm volatile("tcgen05.wait::ld.sync.aligned;" ::: "memory");
}
__device__ __forceinline__ void cp16(uint32_t dst, const void* src) {
    asm volatile("cp.async.cg.shared.global [%0], [%1], 16;" :: "r"(dst), "l"(src) : "memory");
}
#define CP_COMMIT() asm volatile("cp.async.commit_group;" ::: "memory")
#define CP_WAIT0()  asm volatile("cp.async.wait_group 0;" ::: "memory")
#define LDTM_X32(r, a) \
    asm volatile( \
        "tcgen05.ld.sync.aligned.32x32b.x32.b32 " \
        "{%0, %1, %2, %3, %4, %5, %6, %7, " \
        " %8, %9, %10, %11, %12, %13, %14, %15, " \
        " %16, %17, %18, %19, %20, %21, %22, %23, " \
        " %24, %25, %26, %27, %28, %29, %30, %31}, [%32];" \
        : "=r"((r)[0]),  "=r"((r)[1]),  "=r"((r)[2]),  "=r"((r)[3]), \
          "=r"((r)[4]),  "=r"((r)[5]),  "=r"((r)[6]),  "=r"((r)[7]), \
          "=r"((r)[8]),  "=r"((r)[9]),  "=r"((r)[10]), "=r"((r)[11]), \
          "=r"((r)[12]), "=r"((r)[13]), "=r"((r)[14]), "=r"((r)[15]), \
          "=r"((r)[16]), "=r"((r)[17]), "=r"((r)[18]), "=r"((r)[19]), \
          "=r"((r)[20]), "=r"((r)[21]), "=r"((r)[22]), "=r"((r)[23]), \
          "=r"((r)[24]), "=r"((r)[25]), "=r"((r)[26]), "=r"((r)[27]), \
          "=r"((r)[28]), "=r"((r)[29]), "=r"((r)[30]), "=r"((r)[31]) \
        : "r"(a))

// tf32 SS-mode MMA: D[tmem] (+)= A(smem desc) * B(smem desc)^T, K=8 per call.
__device__ __forceinline__ void mma_tf32_ss(uint32_t d, uint64_t a_desc, uint64_t b_desc,
                                            uint32_t idesc, uint32_t en) {
    asm volatile(
        "{\n\t.reg .pred p;\n\t"
        "setp.ne.u32 p, %5, 0;\n\t"
        "tcgen05.mma.cta_group::1.kind::tf32 [%0], %1, %2, %3, {%4, %4, %4, %4}, p;\n\t"
        "}"
        :: "r"(d), "l"(a_desc), "l"(b_desc), "r"(idesc), "r"(0u), "r"(en)
        : "memory");
}
#endif  // HAS_TCGEN05

__device__ __forceinline__ uint32_t smem_u32(const void* p) {
    uint32_t a;
    asm("{ .reg .u64 t; cvta.to.shared.u64 t, %1; cvt.u32.u64 %0, t; }" : "=r"(a) : "l"(p));
    return a;
}
__device__ __forceinline__ uint32_t sw128(uint32_t off) {
    return off ^ ((off >> 3) & 0x70);
}

// SW128 K-major smem descriptor base: layout=SW128(2), version=1, SBO=64, LBO=1
static constexpr uint64_t DESC_BASE_SW128 =
    (uint64_t(2) << 61) | (uint64_t(1) << 46) | (uint64_t(64) << 32) | (uint64_t(1) << 16);
__device__ __forceinline__ uint64_t make_desc(uint32_t addr) {
    return DESC_BASE_SW128 | ((uint64_t)(addr >> 4) & 0x3FFF);
}

// idesc kind::tf32, D=F32, A=B=TF32 K-major, M=128
__device__ __forceinline__ constexpr uint32_t idesc_tf32(int n) {
    return (1u << 4) | (2u << 7) | (2u << 10) | ((uint32_t)(n / 8) << 17) | (8u << 24);
}

// Mask split: hi keeps tf32-representable top bits exactly; lo = x - hi (exact FADD).
__device__ __forceinline__ void split2(float x, float& hi, float& lo) {
    hi = __uint_as_float(__float_as_uint(x) & 0xFFFFE000u);
    lo = x - hi;
}
__device__ __forceinline__ float hi_part(float x) {
    return __uint_as_float(__float_as_uint(x) & 0xFFFFE000u);
}

// ---------------------------------------------------------------------------
// Weight pre-split: w -> (hi, lo). Tiny; runs once per launch.
// ---------------------------------------------------------------------------
__global__ __launch_bounds__(256) void split_kernel(const float* __restrict__ src,
                                                    float* __restrict__ hi,
                                                    float* __restrict__ lo, int n)
{
    int i = blockIdx.x * 256 + threadIdx.x;
    if (i < n) {
        float x = src[i];
        float h = hi_part(x);
        hi[i] = h;
        lo[i] = x - h;
    }
}

// ---------------------------------------------------------------------------
// Feature generation (R10 version; unsplit output).
// ---------------------------------------------------------------------------
__global__ __launch_bounds__(224) void featgen_kernel(const float* __restrict__ x) {
    int m = blockIdx.x;
    int b = m / 144;
    int p = m - b * 144;
    int h = p / 12;
    int w = p - h * 12;

    __shared__ float sx[168];
    int tid = threadIdx.x;
    if (tid < 168) sx[tid] = (tid == 167) ? 0.f : __ldg(&x[b * 168 + tid]);
    __syncthreads();

    if (tid < 196) {
        int i1 = tid / 14;
        int j1 = tid - i1 * 14;
        float xi = sx[i1 * 12 + h];
        float xj = sx[j1 * 12 + w];
        float d  = xj - xi;
        float r  = __frcp_rn(xi + xj + EPSF);
        float* o = &g_F[(size_t)m * 588 + tid * 3];
        o[0] = d;
        o[1] = d * r;
        o[2] = xj * r;
    }
}

// ---------------------------------------------------------------------------
// GEMM + bias + ReLU:  C[m, n0+j] = relu( sum_k A[m,k] * W[n0+j,k] + bias )
// A: unsplit DRAM -> LDG reg-prefetch -> mask-split -> STS hi/lo (R10 path).
// B: pre-split DRAM -> cp.async.cg into hi/lo stages, issued one chunk ahead.
// CTA tile 128 x NT; K chunks of 32; double-buffered stages; 512 threads.
// ---------------------------------------------------------------------------
template<int NT, int N, int K>
__global__ __launch_bounds__(512)
void gemm_tc_kernel(const float* __restrict__ A,
                    const float* __restrict__ Bhi_g, const float* __restrict__ Blo_g,
                    const float* __restrict__ bias, float* __restrict__ C)
{
    extern __shared__ char smem[];
#if HAS_TCGEN05
    static_assert(NT % 64 == 0 && NT <= 256 && N % NT == 0 && K % 4 == 0, "tile assumptions");
    constexpr int BK  = 32;
    constexpr int T   = (K + BK - 1) / BK;
    constexpr int TAILV = (K % BK) / 4;          // valid float4 slots in tail (0 = exact)
    constexpr int SLB = NT * 8 / 512;            // B 16B-chunks per thread per half
    constexpr int AHI = 0, ALO = 16384, BHI = 32768;
    constexpr int BLO   = BHI + NT * 128;
    constexpr int STAGE = 32768 + 2 * NT * 128;
    constexpr int TILE0 = 1024;
    constexpr uint32_t ID = idesc_tf32(NT);

    const uint32_t sbase = smem_u32(smem);
    const int tid = threadIdx.x;
    const int wid = tid >> 5, lid = tid & 31;
    const int m0 = blockIdx.x * 128;
    const int n0 = blockIdx.y * NT;

    if (wid == 0) {
        tmem_alloc(sbase, 512);
        tmem_relinquish();
    }
    if (tid == 0) { mbar_init(sbase + 8, 1); mbar_init(sbase + 16, 1); }
    __syncthreads();
    uint32_t tmem;
    asm volatile("ld.shared.b32 %0, [%1];" : "=r"(tmem) : "r"(sbase));

    const float* zsrc = g_zero16;
    const ptrdiff_t dB = Blo_g - Bhi_g;

    // ---- A geometry: 1024 float4 slots, 2 per thread ----
    const float* aPtr[2];
    uint32_t offA[2];
    int c4A[2];
#pragma unroll
    for (int p = 0; p < 2; ++p) {
        int slot = tid + p * 512;
        int row  = slot >> 3;
        int c4   = (slot & 7) * 4;
        aPtr[p]  = &A[(size_t)(m0 + row) * K + c4];
        offA[p]  = sw128(row * 128 + c4 * 4);
        c4A[p]   = c4;
    }
    // ---- B geometry: NT*8 16B-chunks per half, SLB per thread ----
    const float* bSrc[SLB];
    uint32_t offB[SLB];
    int c4B[SLB];
#pragma unroll
    for (int p = 0; p < SLB; ++p) {
        int slot = tid + p * 512;
        int row  = slot >> 3;
        int c4   = slot & 7;
        bSrc[p]  = &Bhi_g[(size_t)(n0 + row) * K + c4 * 4];
        offB[p]  = sw128(row * 128 + c4 * 16);
        c4B[p]   = c4;
    }

    auto issue_B = [&](int c) {
        const uint32_t stage = sbase + TILE0 + (c & 1) * STAGE;
        const bool tail = (TAILV > 0) && (c == T - 1);
        const int koff = c * BK;
#pragma unroll
        for (int p = 0; p < SLB; ++p) {
            bool ok = !tail || (c4B[p] < TAILV);
            cp16(stage + BHI + offB[p], ok ? (bSrc[p] + koff) : zsrc);
            cp16(stage + BLO + offB[p], ok ? (bSrc[p] + koff + dB) : zsrc);
        }
        CP_COMMIT();
    };

    // preamble: A chunk 0 into regs, B chunk 0 in flight
    float4 pa[2];
#pragma unroll
    for (int p = 0; p < 2; ++p)
        pa[p] = (c4A[p] < K) ? *reinterpret_cast<const float4*>(aPtr[p])
                             : make_float4(0.f, 0.f, 0.f, 0.f);
    issue_B(0);

#pragma unroll 1
    for (int t = 0; t < T; ++t) {
        // prefetch A chunk t+1 into regs (latency hidden behind this chunk)
        float4 na[2];
        if (t + 1 < T) {
            const int k1 = (t + 1) * BK;
#pragma unroll
            for (int p = 0; p < 2; ++p)
                na[p] = (k1 + c4A[p] < K) ? *reinterpret_cast<const float4*>(aPtr[p] + k1)
                                          : make_float4(0.f, 0.f, 0.f, 0.f);
        }

        const int buf = t & 1;
        char* stage = smem + TILE0 + buf * STAGE;

        // ---- A: mask-split + STS (buffer freed by end-of-iter wait below) ----
#pragma unroll
        for (int p = 0; p < 2; ++p) {
            float4 h, l;
            split2(pa[p].x, h.x, l.x); split2(pa[p].y, h.y, l.y);
            split2(pa[p].z, h.z, l.z); split2(pa[p].w, h.w, l.w);
            *reinterpret_cast<float4*>(stage + AHI + offA[p]) = h;
            *reinterpret_cast<float4*>(stage + ALO + offA[p]) = l;
        }
        CP_WAIT0();          // B chunk t complete (issued one iteration ago)
        asm volatile("fence.proxy.async.shared::cta;" ::: "memory");
        __syncthreads();

        if (wid == 0 && elect_one()) {
            const uint32_t base = sbase + TILE0 + buf * STAGE;
            uint64_t dAhi = make_desc(base + AHI);
            uint64_t dAlo = make_desc(base + ALO);
            uint64_t dBhi = make_desc(base + BHI);
            uint64_t dBlo = make_desc(base + BLO);
#pragma unroll
            for (int kk = 0; kk < 4; ++kk) {
                uint32_t en0 = (t > 0 || kk > 0) ? 1u : 0u;
                mma_tf32_ss(tmem, dAhi + kk * 2, dBhi + kk * 2, ID, en0);
                mma_tf32_ss(tmem, dAhi + kk * 2, dBlo + kk * 2, ID, 1u);
                mma_tf32_ss(tmem, dAlo + kk * 2, dBhi + kk * 2, ID, 1u);
            }
            tc_commit(sbase + 8 + 8 * buf);
        }

        // free buffer (t+1)&1 (wait MMA t-1), then launch B chunk t+1 into it
        if (t + 1 < T) {
            if (t >= 1) mbar_wait(sbase + 8 + 8 * ((t - 1) & 1), ((t - 1) >> 1) & 1);
            issue_B(t + 1);
        }
#pragma unroll
        for (int p = 0; p < 2; ++p) pa[p] = na[p];
    }

    // Wait for the last commit (tensor pipe is in-order), then read D.
    mbar_wait(sbase + 8 + 8 * ((T - 1) & 1), ((T - 1) >> 1) & 1);
    tc_fence_after();

    // epilogue: warps 0-7; warp w = subpartition w&3, col half w>>2
    if (wid < 8) {
        const int m = m0 + (wid & 3) * 32 + lid;
        const int ch0 = (wid >> 2) * (NT / 2);
        float* crow = &C[(size_t)m * N + n0];
#pragma unroll
        for (int c0 = ch0; c0 < ch0 + NT / 2; c0 += 32) {
            uint32_t r[32];
            LDTM_X32(r, tmem + c0);
            tc_wait_ld();
#pragma unroll
            for (int j = 0; j < 32; j += 4) {
                float4 v;
                v.x = fmaxf(__uint_as_float(r[j + 0]) + __ldg(&bias[n0 + c0 + j + 0]), 0.f);
                v.y = fmaxf(__uint_as_float(r[j + 1]) + __ldg(&bias[n0 + c0 + j + 1]), 0.f);
                v.z = fmaxf(__uint_as_float(r[j + 2]) + __ldg(&bias[n0 + c0 + j + 2]), 0.f);
                v.w = fmaxf(__uint_as_float(r[j + 3]) + __ldg(&bias[n0 + c0 + j + 3]), 0.f);
                *reinterpret_cast<float4*>(crow + c0 + j) = v;
            }
        }
        tc_fence_before();
    }
    __syncthreads();
    if (wid == 0) tmem_dealloc(tmem, 512);

#else  // ---------------- SIMT fp32 fallback (plain sm_103 cubin) ----------
    float (*As)[130] = reinterpret_cast<float (*)[130]>(smem);               // [16][130]
    float (*Bs)[66]  = reinterpret_cast<float (*)[66]>(smem + 16 * 130 * 4); // [16][66]

    const int tid = threadIdx.x;
    const int m0 = blockIdx.x * 128;
    const int nbase = blockIdx.y * NT;
    const int tx = tid & 15;
    const int ty = (tid & 255) >> 4;
    const int ntiles = (K + 15) / 16;

    for (int n0 = nbase; n0 < nbase + NT; n0 += 64) {
        float acc[8][4];
#pragma unroll
        for (int i = 0; i < 8; ++i)
#pragma unroll
            for (int j = 0; j < 4; ++j) acc[i][j] = 0.f;

        for (int t = 0; t < ntiles; ++t) {
            int k0 = t * 16;
            {   // A tile: 512 float4 slots, one per thread
                int idx = tid;
                int ml  = idx >> 2;
                int kl  = (idx & 3) * 4;
                int gk  = k0 + kl;
                float4 v = make_float4(0.f, 0.f, 0.f, 0.f);
                if (gk < K)
                    v = *reinterpret_cast<const float4*>(&A[(size_t)(m0 + ml) * K + gk]);
                As[kl + 0][ml] = v.x; As[kl + 1][ml] = v.y;
                As[kl + 2][ml] = v.z; As[kl + 3][ml] = v.w;
            }
            if (tid < 256) {  // B tile: 256 slots (hi+lo recombined)
                int idx = tid;
                int nl  = idx >> 2;
                int kl  = (idx & 3) * 4;
                int gk  = k0 + kl;
                float4 v = make_float4(0.f, 0.f, 0.f, 0.f);
                if (gk < K) {
                    size_t o = (size_t)(n0 + nl) * K + gk;
                    float4 h = *reinterpret_cast<const float4*>(&Bhi_g[o]);
                    float4 l = *reinterpret_cast<const float4*>(&Blo_g[o]);
                    v.x = h.x + l.x; v.y = h.y + l.y; v.z = h.z + l.z; v.w = h.w + l.w;
                }
                Bs[kl + 0][nl] = v.x; Bs[kl + 1][nl] = v.y;
                Bs[kl + 2][nl] = v.z; Bs[kl + 3][nl] = v.w;
            }
            __syncthreads();
            if (tid < 256) {
#pragma unroll
                for (int kk = 0; kk < 16; ++kk) {
                    float a[8], bb[4];
#pragma unroll
                    for (int i = 0; i < 8; ++i) a[i] = As[kk][ty * 8 + i];
#pragma unroll
                    for (int j = 0; j < 4; ++j) bb[j] = Bs[kk][tx * 4 + j];
#pragma unroll
                    for (int i = 0; i < 8; ++i)
#pragma unroll
                        for (int j = 0; j < 4; ++j)
                            acc[i][j] = fmaf(a[i], bb[j], acc[i][j]);
                }
            }
            __syncthreads();
        }

        if (tid < 256) {
#pragma unroll
            for (int i = 0; i < 8; ++i) {
                int m = m0 + ty * 8 + i;
                int n = n0 + tx * 4;
                float4 v;
                v.x = fmaxf(acc[i][0] + bias[n + 0], 0.f);
                v.y = fmaxf(acc[i][1] + bias[n + 1], 0.f);
                v.z = fmaxf(acc[i][2] + bias[n + 2], 0.f);
                v.w = fmaxf(acc[i][3] + bias[n + 3], 0.f);
                *reinterpret_cast<float4*>(&C[(size_t)m * N + n]) = v;
            }
        }
        __syncthreads();
    }
#endif
}

// ---------------------------------------------------------------------------
// Final reduction (unchanged).
// ---------------------------------------------------------------------------
__global__ __launch_bounds__(256) void reduce_kernel(
    const float* __restrict__ wm_in, float* __restrict__ out)
{
    __shared__ float wms[16 * 144];
    __shared__ float rsum[16];
    int b = blockIdx.x;
    int tid = threadIdx.x;

    for (int i = tid; i < 16 * 144; i += 256)
        wms[i] = expf(wm_in[i]);
    __syncthreads();
    if (tid < 16) {
        float s = 0.f;
        for (int p = 0; p < 144; ++p) s += wms[tid * 144 + p];
        rsum[tid] = 1.f / s;
    }
    __syncthreads();

    int g = tid >> 4;
    const float* h2 = g_H2 + (size_t)b * 144 * 256;
    float acc = 0.f;
    for (int p = 0; p < 144; ++p)
        acc = fmaf(h2[p * 256 + tid], wms[g * 144 + p], acc);
    acc *= rsum[g];
    out[b * 256 + tid] = fmaxf(acc, 0.f);
}

// ---------------------------------------------------------------------------
extern "C" void kernel_launch(void* const* d_in, const int* in_sizes, int n_in,
                              void* d_out, int out_size)
{
    const float* x  = (const float*)d_in[0];
    const float* w0 = (const float*)d_in[1];
    const float* b0 = (const float*)d_in[2];
    const float* w1 = (const float*)d_in[3];
    const float* b1 = (const float*)d_in[4];
    const float* w2 = (const float*)d_in[5];
    const float* b2 = (const float*)d_in[6];
    const float* wm = (const float*)d_in[7];
    float* out = (float*)d_out;

    float *F, *H0, *H1, *H2;
    float *W0hi, *W0lo, *W1hi, *W1lo, *W2hi, *W2lo;
    cudaGetSymbolAddress((void**)&F,  g_F);
    cudaGetSymbolAddress((void**)&H0, g_H0);
    cudaGetSymbolAddress((void**)&H1, g_H1);
    cudaGetSymbolAddress((void**)&H2, g_H2);
    cudaGetSymbolAddress((void**)&W0hi, g_W0hi);
    cudaGetSymbolAddress((void**)&W0lo, g_W0lo);
    cudaGetSymbolAddress((void**)&W1hi, g_W1hi);
    cudaGetSymbolAddress((void**)&W1lo, g_W1lo);
    cudaGetSymbolAddress((void**)&W2hi, g_W2hi);
    cudaGetSymbolAddress((void**)&W2lo, g_W2lo);

    // SMEM: ctrl 1024 + 2 stages * (32768 + 2*NT*128)
    constexpr int S0 = 1024 + 2 * (32768 + 2 * 256 * 128);  // 197632 (NT=256)
    constexpr int S1 = 1024 + 2 * (32768 + 2 * 192 * 128);  // 164864 (NT=192)
    constexpr int S2 = 1024 + 2 * (32768 + 2 * 256 * 128);  // 197632 (NT=256)
    cudaFuncSetAttribute(gemm_tc_kernel<256, 512, 588>, cudaFuncAttributeMaxDynamicSharedMemorySize, S0);
    cudaFuncSetAttribute(gemm_tc_kernel<192, 384, 512>, cudaFuncAttributeMaxDynamicSharedMemorySize, S1);
    cudaFuncSetAttribute(gemm_tc_kernel<256, 256, 384>, cudaFuncAttributeMaxDynamicSharedMemorySize, S2);

    // weight pre-split (tiny; graph-capturable)
    split_kernel<<<(512 * 588 + 255) / 256, 256>>>(w0, W0hi, W0lo, 512 * 588);
    split_kernel<<<(384 * 512 + 255) / 256, 256>>>(w1, W1hi, W1lo, 384 * 512);
    split_kernel<<<(256 * 384 + 255) / 256, 256>>>(w2, W2hi, W2lo, 256 * 384);

    featgen_kernel<<<M_TOTAL, 224>>>(x);

    gemm_tc_kernel<256, 512, 588><<<dim3(M_TOTAL / 128, 2), 512, S0>>>(F,  W0hi, W0lo, b0, H0);
    gemm_tc_kernel<192, 384, 512><<<dim3(M_TOTAL / 128, 2), 512, S1>>>(H0, W1hi, W1lo, b1, H1);
    gemm_tc_kernel<256, 256, 384><<<dim3(M_TOTAL / 128, 1), 512, S2>>>(H1, W2hi, W2lo, b2, H2);

    reduce_kernel<<<1024, 256>>>(wm, out);
}

// round 17
// speedup vs baseline: 2.4790x; 1.6623x over previous
#include <cuda_runtime.h>
#include <cstdint>
#include <math.h>

// ---------------------------------------------------------------------------
// TSI_Encoder, round 15: exact R10 mainloop (best known, 1286us) plus:
//   1) grid swap: n-tile is the fastest grid dim -> same-m CTAs co-resident,
//      A tiles served from L2 on the second n-tile (saves ~500MB DRAM).
//   2) MMA order AhiBhi, AloBhi, AhiBlo (adjacent dispatches share Bhi).
//   3) featgen writes staged in SMEM -> coalesced float4 stores.
// Producer restructures (cg2 R8, TS-A R9, cp.async R11-13) all regressed and
// stay reverted.
// ---------------------------------------------------------------------------

#define EPSF 1e-5f
#define M_TOTAL 147456   // 1024 * 144

#if defined(__CUDA_ARCH_FEAT_SM103_ALL) || defined(__CUDA_ARCH_FEAT_SM101_ALL) || \
    defined(__CUDA_ARCH_FEAT_SM100_ALL) ||                                        \
    (defined(__CUDA_ARCH_SPECIFIC__) && (__CUDA_ARCH_SPECIFIC__ >= 1000)) ||      \
    (defined(__CUDA_ARCH_FAMILY_SPECIFIC__) && (__CUDA_ARCH_FAMILY_SPECIFIC__ >= 1000))
#define HAS_TCGEN05 1
#else
#define HAS_TCGEN05 0
#endif

__device__ float g_F [147456ULL * 588];
__device__ float g_H0[147456ULL * 512];
__device__ float g_H1[147456ULL * 384];
__device__ float g_H2[147456ULL * 256];

// ======================== inline PTX helpers (103a-only) ====================
#if HAS_TCGEN05
__device__ __forceinline__ uint32_t elect_one() {
    uint32_t pred;
    asm volatile("{\n\t.reg .pred p;\n\telect.sync _|p, 0xFFFFFFFF;\n\tselp.b32 %0, 1, 0, p;\n\t}"
                 : "=r"(pred));
    return pred;
}
__device__ __forceinline__ void mbar_init(uint32_t addr, uint32_t cnt) {
    asm volatile("mbarrier.init.shared.b64 [%0], %1;" :: "r"(addr), "r"(cnt) : "memory");
}
__device__ __forceinline__ void mbar_wait(uint32_t mbar, uint32_t parity) {
    asm volatile(
        "{\n\t.reg .pred P1;\n\t"
        "WAIT_LOOP_%=:\n\t"
        "mbarrier.try_wait.parity.acquire.cta.shared::cta.b64 P1, [%0], %1, 0x989680;\n\t"
        "@P1 bra.uni WAIT_DONE_%=;\n\t"
        "bra.uni WAIT_LOOP_%=;\n\t"
        "WAIT_DONE_%=:\n\t}"
        :: "r"(mbar), "r"(parity) : "memory");
}
__device__ __forceinline__ void tmem_alloc(uint32_t dst_smem, uint32_t ncols) {
    asm volatile("tcgen05.alloc.cta_group::1.sync.aligned.shared::cta.b32 [%0], %1;"
                 :: "r"(dst_smem), "r"(ncols) : "memory");
}
__device__ __forceinline__ void tmem_relinquish() {
    asm volatile("tcgen05.relinquish_alloc_permit.cta_group::1.sync.aligned;");
}
__device__ __forceinline__ void tmem_dealloc(uint32_t tmem, uint32_t ncols) {
    asm volatile("tcgen05.dealloc.cta_group::1.sync.aligned.b32 %0, %1;" :: "r"(tmem), "r"(ncols));
}
__device__ __forceinline__ void tc_commit(uint32_t mbar) {
    asm volatile("tcgen05.commit.cta_group::1.mbarrier::arrive::one.shared::cluster.b64 [%0];"
                 :: "r"(mbar) : "memory");
}
__device__ __forceinline__ void tc_fence_after() {
    asm volatile("tcgen05.fence::after_thread_sync;" ::: "memory");
}
__device__ __forceinline__ void tc_fence_before() {
    asm volatile("tcgen05.fence::before_thread_sync;" ::: "memory");
}
__device__ __forceinline__ void tc_wait_ld() {
    asm volatile("tcgen05.wait::ld.sync.aligned;" ::: "memory");
}
#define LDTM_X32(r, a) \
    asm volatile( \
        "tcgen05.ld.sync.aligned.32x32b.x32.b32 " \
        "{%0, %1, %2, %3, %4, %5, %6, %7, " \
        " %8, %9, %10, %11, %12, %13, %14, %15, " \
        " %16, %17, %18, %19, %20, %21, %22, %23, " \
        " %24, %25, %26, %27, %28, %29, %30, %31}, [%32];" \
        : "=r"((r)[0]),  "=r"((r)[1]),  "=r"((r)[2]),  "=r"((r)[3]), \
          "=r"((r)[4]),  "=r"((r)[5]),  "=r"((r)[6]),  "=r"((r)[7]), \
          "=r"((r)[8]),  "=r"((r)[9]),  "=r"((r)[10]), "=r"((r)[11]), \
          "=r"((r)[12]), "=r"((r)[13]), "=r"((r)[14]), "=r"((r)[15]), \
          "=r"((r)[16]), "=r"((r)[17]), "=r"((r)[18]), "=r"((r)[19]), \
          "=r"((r)[20]), "=r"((r)[21]), "=r"((r)[22]), "=r"((r)[23]), \
          "=r"((r)[24]), "=r"((r)[25]), "=r"((r)[26]), "=r"((r)[27]), \
          "=r"((r)[28]), "=r"((r)[29]), "=r"((r)[30]), "=r"((r)[31]) \
        : "r"(a))

// tf32 SS-mode MMA: D[tmem] (+)= A(smem desc) * B(smem desc)^T, K=8 per call.
__device__ __forceinline__ void mma_tf32_ss(uint32_t d, uint64_t a_desc, uint64_t b_desc,
                                            uint32_t idesc, uint32_t en) {
    asm volatile(
        "{\n\t.reg .pred p;\n\t"
        "setp.ne.u32 p, %5, 0;\n\t"
        "tcgen05.mma.cta_group::1.kind::tf32 [%0], %1, %2, %3, {%4, %4, %4, %4}, p;\n\t"
        "}"
        :: "r"(d), "l"(a_desc), "l"(b_desc), "r"(idesc), "r"(0u), "r"(en)
        : "memory");
}
#endif  // HAS_TCGEN05

__device__ __forceinline__ uint32_t smem_u32(const void* p) {
    uint32_t a;
    asm("{ .reg .u64 t; cvta.to.shared.u64 t, %1; cvt.u32.u64 %0, t; }" : "=r"(a) : "l"(p));
    return a;
}
__device__ __forceinline__ uint32_t sw128(uint32_t off) {
    return off ^ ((off >> 3) & 0x70);
}

// SW128 K-major smem descriptor base: layout=SW128(2), version=1, SBO=64, LBO=1
static constexpr uint64_t DESC_BASE_SW128 =
    (uint64_t(2) << 61) | (uint64_t(1) << 46) | (uint64_t(64) << 32) | (uint64_t(1) << 16);
__device__ __forceinline__ uint64_t make_desc(uint32_t addr) {
    return DESC_BASE_SW128 | ((uint64_t)(addr >> 4) & 0x3FFF);
}

// idesc kind::tf32, D=F32, A=B=TF32 K-major, M=128
__device__ __forceinline__ constexpr uint32_t idesc_tf32(int n) {
    return (1u << 4) | (2u << 7) | (2u << 10) | ((uint32_t)(n / 8) << 17) | (8u << 24);
}

// Mask split: hi keeps tf32-representable top bits exactly; lo = x - hi (exact FADD).
__device__ __forceinline__ void split2(float x, float& hi, float& lo) {
    hi = __uint_as_float(__float_as_uint(x) & 0xFFFFE000u);
    lo = x - hi;
}

// ---------------------------------------------------------------------------
// Feature generation: row staged in SMEM, then coalesced float4 stores.
// Numerics identical to R10 (same ops, only the store path changes).
// ---------------------------------------------------------------------------
__global__ __launch_bounds__(224) void featgen_kernel(const float* __restrict__ x) {
    int m = blockIdx.x;
    int b = m / 144;
    int p = m - b * 144;
    int h = p / 12;
    int w = p - h * 12;

    __shared__ float sx[168];
    __shared__ float row[588];
    int tid = threadIdx.x;
    if (tid < 168) sx[tid] = (tid == 167) ? 0.f : __ldg(&x[b * 168 + tid]);
    __syncthreads();

    if (tid < 196) {
        int i1 = tid / 14;
        int j1 = tid - i1 * 14;
        float xi = sx[i1 * 12 + h];
        float xj = sx[j1 * 12 + w];
        float d  = xj - xi;
        float r  = __frcp_rn(xi + xj + EPSF);
        row[tid * 3 + 0] = d;
        row[tid * 3 + 1] = d * r;
        row[tid * 3 + 2] = xj * r;
    }
    __syncthreads();

    // 588 floats = 147 float4, coalesced
    float4* dst = reinterpret_cast<float4*>(&g_F[(size_t)m * 588]);
    const float4* src = reinterpret_cast<const float4*>(row);
    if (tid < 147) dst[tid] = src[tid];
}

// ---------------------------------------------------------------------------
// GEMM + bias + ReLU:  C[m, n0+j] = relu( sum_k A[m,k] * W[n0+j,k] + bias )
// EXACT R10 mainloop. Grid: x = n-tile (fastest -> L2 A-sharing), y = m-tile.
// MMA order per kk: AhiBhi, AloBhi (shares Bhi), AhiBlo.
// ---------------------------------------------------------------------------
template<int NT, int N, int K>
__global__ __launch_bounds__(512)
void gemm_tc_kernel(const float* __restrict__ A, const float* __restrict__ W,
                    const float* __restrict__ bias, float* __restrict__ C)
{
    extern __shared__ char smem[];
#if HAS_TCGEN05
    static_assert(NT % 64 == 0 && NT <= 256 && N % NT == 0 && K % 4 == 0, "tile assumptions");
    constexpr int BK  = 32;
    constexpr int T   = (K + BK - 1) / BK;
    constexpr int SLB = NT * 8 / 512;            // B float4 slots per thread (4 / 3)
    constexpr int AHI = 0, ALO = 16384, BHI = 32768;
    constexpr int BLO   = BHI + NT * 128;
    constexpr int STAGE = 32768 + 2 * NT * 128;
    constexpr int TILE0 = 1024;
    constexpr uint32_t ID = idesc_tf32(NT);

    const uint32_t sbase = smem_u32(smem);
    const int tid = threadIdx.x;
    const int wid = tid >> 5, lid = tid & 31;
    const int m0 = blockIdx.y * 128;             // m-tile: slow grid dim
    const int n0 = blockIdx.x * NT;              // n-tile: fast grid dim (L2 share A)

    if (wid == 0) {
        tmem_alloc(sbase, 512);
        tmem_relinquish();
    }
    if (tid == 0) { mbar_init(sbase + 8, 1); mbar_init(sbase + 16, 1); }
    __syncthreads();
    uint32_t tmem;
    asm volatile("ld.shared.b32 %0, [%1];" : "=r"(tmem) : "r"(sbase));

    // ---- per-thread slot geometry (k-invariant): pointers + smem offsets ----
    const float* aPtr[2];
    uint32_t offA[2];
    int c4A[2];
#pragma unroll
    for (int p = 0; p < 2; ++p) {
        int slot = tid + p * 512;                // 1024 A slots
        int row  = slot >> 3;
        int c4   = (slot & 7) * 4;
        aPtr[p]  = &A[(size_t)(m0 + row) * K + c4];
        offA[p]  = sw128(row * 128 + c4 * 4);
        c4A[p]   = c4;
    }
    const float* bPtr[SLB];
    uint32_t offB[SLB];
    int c4B[SLB];
#pragma unroll
    for (int p = 0; p < SLB; ++p) {
        int slot = tid + p * 512;                // NT*8 B slots
        int row  = slot >> 3;
        int c4   = (slot & 7) * 4;
        bPtr[p]  = &W[(size_t)(n0 + row) * K + c4];
        offB[p]  = sw128(row * 128 + c4 * 4);
        c4B[p]   = c4;
    }

    float4 pa[2], pb[SLB];
    // preamble: load chunk 0
#pragma unroll
    for (int p = 0; p < 2; ++p)
        pa[p] = (c4A[p] < K) ? *reinterpret_cast<const float4*>(aPtr[p])
                             : make_float4(0.f, 0.f, 0.f, 0.f);
#pragma unroll
    for (int p = 0; p < SLB; ++p)
        pb[p] = (c4B[p] < K) ? *reinterpret_cast<const float4*>(bPtr[p])
                             : make_float4(0.f, 0.f, 0.f, 0.f);

#pragma unroll 1
    for (int t = 0; t < T; ++t) {
        // ---- issue next chunk's loads first (latency hidden behind this chunk) ----
        float4 na[2], nb[SLB];
        if (t + 1 < T) {
            const int k1 = (t + 1) * BK;
#pragma unroll
            for (int p = 0; p < 2; ++p)
                na[p] = (k1 + c4A[p] < K) ? *reinterpret_cast<const float4*>(aPtr[p] + k1)
                                          : make_float4(0.f, 0.f, 0.f, 0.f);
#pragma unroll
            for (int p = 0; p < SLB; ++p)
                nb[p] = (k1 + c4B[p] < K) ? *reinterpret_cast<const float4*>(bPtr[p] + k1)
                                          : make_float4(0.f, 0.f, 0.f, 0.f);
        }

        const int buf = t & 1;
        char* stage = smem + TILE0 + buf * STAGE;
        if (t >= 2) mbar_wait(sbase + 8 + 8 * buf, ((t - 2) >> 1) & 1);

        // ---- mask-split + STS (alu/fma pipes; no cvt) ----
#pragma unroll
        for (int p = 0; p < 2; ++p) {
            float4 h, l;
            split2(pa[p].x, h.x, l.x); split2(pa[p].y, h.y, l.y);
            split2(pa[p].z, h.z, l.z); split2(pa[p].w, h.w, l.w);
            *reinterpret_cast<float4*>(stage + AHI + offA[p]) = h;
            *reinterpret_cast<float4*>(stage + ALO + offA[p]) = l;
        }
#pragma unroll
        for (int p = 0; p < SLB; ++p) {
            float4 h, l;
            split2(pb[p].x, h.x, l.x); split2(pb[p].y, h.y, l.y);
            split2(pb[p].z, h.z, l.z); split2(pb[p].w, h.w, l.w);
            *reinterpret_cast<float4*>(stage + BHI + offB[p]) = h;
            *reinterpret_cast<float4*>(stage + BLO + offB[p]) = l;
        }
        asm volatile("fence.proxy.async.shared::cta;" ::: "memory");
        __syncthreads();

        if (wid == 0 && elect_one()) {
            const uint32_t base = sbase + TILE0 + buf * STAGE;
            uint64_t dAhi = make_desc(base + AHI);
            uint64_t dAlo = make_desc(base + ALO);
            uint64_t dBhi = make_desc(base + BHI);
            uint64_t dBlo = make_desc(base + BLO);
#pragma unroll
            for (int kk = 0; kk < 4; ++kk) {
                uint32_t en0 = (t > 0 || kk > 0) ? 1u : 0u;
                mma_tf32_ss(tmem, dAhi + kk * 2, dBhi + kk * 2, ID, en0);
                mma_tf32_ss(tmem, dAlo + kk * 2, dBhi + kk * 2, ID, 1u);  // shares Bhi
                mma_tf32_ss(tmem, dAhi + kk * 2, dBlo + kk * 2, ID, 1u);
            }
            tc_commit(sbase + 8 + 8 * buf);
        }

        // rotate prefetch registers
#pragma unroll
        for (int p = 0; p < 2; ++p) pa[p] = na[p];
#pragma unroll
        for (int p = 0; p < SLB; ++p) pb[p] = nb[p];
    }

    // Wait for the last commit (tensor pipe is in-order), then read D.
    mbar_wait(sbase + 8 + 8 * ((T - 1) & 1), ((T - 1) >> 1) & 1);
    tc_fence_after();

    // epilogue: warps 0-7; warp w = subpartition w&3, col half w>>2
    if (wid < 8) {
        const int m = m0 + (wid & 3) * 32 + lid;
        const int ch0 = (wid >> 2) * (NT / 2);
        float* crow = &C[(size_t)m * N + n0];
#pragma unroll
        for (int c0 = ch0; c0 < ch0 + NT / 2; c0 += 32) {
            uint32_t r[32];
            LDTM_X32(r, tmem + c0);
            tc_wait_ld();
#pragma unroll
            for (int j = 0; j < 32; j += 4) {
                float4 v;
                v.x = fmaxf(__uint_as_float(r[j + 0]) + __ldg(&bias[n0 + c0 + j + 0]), 0.f);
                v.y = fmaxf(__uint_as_float(r[j + 1]) + __ldg(&bias[n0 + c0 + j + 1]), 0.f);
                v.z = fmaxf(__uint_as_float(r[j + 2]) + __ldg(&bias[n0 + c0 + j + 2]), 0.f);
                v.w = fmaxf(__uint_as_float(r[j + 3]) + __ldg(&bias[n0 + c0 + j + 3]), 0.f);
                *reinterpret_cast<float4*>(crow + c0 + j) = v;
            }
        }
        tc_fence_before();
    }
    __syncthreads();
    if (wid == 0) tmem_dealloc(tmem, 512);

#else  // ---------------- SIMT fp32 fallback (plain sm_103 cubin) ----------
    float (*As)[130] = reinterpret_cast<float (*)[130]>(smem);               // [16][130]
    float (*Bs)[66]  = reinterpret_cast<float (*)[66]>(smem + 16 * 130 * 4); // [16][66]

    const int tid = threadIdx.x;
    const int m0 = blockIdx.y * 128;
    const int nbase = blockIdx.x * NT;
    const int tx = tid & 15;
    const int ty = (tid & 255) >> 4;
    const int ntiles = (K + 15) / 16;

    for (int n0 = nbase; n0 < nbase + NT; n0 += 64) {
        float acc[8][4];
#pragma unroll
        for (int i = 0; i < 8; ++i)
#pragma unroll
            for (int j = 0; j < 4; ++j) acc[i][j] = 0.f;

        for (int t = 0; t < ntiles; ++t) {
            int k0 = t * 16;
            {   // A tile: 512 float4 slots, one per thread
                int idx = tid;
                int ml  = idx >> 2;
                int kl  = (idx & 3) * 4;
                int gk  = k0 + kl;
                float4 v = make_float4(0.f, 0.f, 0.f, 0.f);
                if (gk < K)
                    v = *reinterpret_cast<const float4*>(&A[(size_t)(m0 + ml) * K + gk]);
                As[kl + 0][ml] = v.x; As[kl + 1][ml] = v.y;
                As[kl + 2][ml] = v.z; As[kl + 3][ml] = v.w;
            }
            if (tid < 256) {  // B tile: 256 slots
                int idx = tid;
                int nl  = idx >> 2;
                int kl  = (idx & 3) * 4;
                int gk  = k0 + kl;
                float4 v = make_float4(0.f, 0.f, 0.f, 0.f);
                if (gk < K)
                    v = *reinterpret_cast<const float4*>(&W[(size_t)(n0 + nl) * K + gk]);
                Bs[kl + 0][nl] = v.x; Bs[kl + 1][nl] = v.y;
                Bs[kl + 2][nl] = v.z; Bs[kl + 3][nl] = v.w;
            }
            __syncthreads();
            if (tid < 256) {
#pragma unroll
                for (int kk = 0; kk < 16; ++kk) {
                    float a[8], bb[4];
#pragma unroll
                    for (int i = 0; i < 8; ++i) a[i] = As[kk][ty * 8 + i];
#pragma unroll
                    for (int j = 0; j < 4; ++j) bb[j] = Bs[kk][tx * 4 + j];
#pragma unroll
                    for (int i = 0; i < 8; ++i)
#pragma unroll
                        for (int j = 0; j < 4; ++j)
                            acc[i][j] = fmaf(a[i], bb[j], acc[i][j]);
                }
            }
            __syncthreads();
        }

        if (tid < 256) {
#pragma unroll
            for (int i = 0; i < 8; ++i) {
                int m = m0 + ty * 8 + i;
                int n = n0 + tx * 4;
                float4 v;
                v.x = fmaxf(acc[i][0] + bias[n + 0], 0.f);
                v.y = fmaxf(acc[i][1] + bias[n + 1], 0.f);
                v.z = fmaxf(acc[i][2] + bias[n + 2], 0.f);
                v.w = fmaxf(acc[i][3] + bias[n + 3], 0.f);
                *reinterpret_cast<float4*>(&C[(size_t)m * N + n]) = v;
            }
        }
        __syncthreads();
    }
#endif
}

// ---------------------------------------------------------------------------
// Final reduction (unchanged).
// ---------------------------------------------------------------------------
__global__ __launch_bounds__(256) void reduce_kernel(
    const float* __restrict__ wm_in, float* __restrict__ out)
{
    __shared__ float wms[16 * 144];
    __shared__ float rsum[16];
    int b = blockIdx.x;
    int tid = threadIdx.x;

    for (int i = tid; i < 16 * 144; i += 256)
        wms[i] = expf(wm_in[i]);
    __syncthreads();
    if (tid < 16) {
        float s = 0.f;
        for (int p = 0; p < 144; ++p) s += wms[tid * 144 + p];
        rsum[tid] = 1.f / s;
    }
    __syncthreads();

    int g = tid >> 4;
    const float* h2 = g_H2 + (size_t)b * 144 * 256;
    float acc = 0.f;
    for (int p = 0; p < 144; ++p)
        acc = fmaf(h2[p * 256 + tid], wms[g * 144 + p], acc);
    acc *= rsum[g];
    out[b * 256 + tid] = fmaxf(acc, 0.f);
}

// ---------------------------------------------------------------------------
extern "C" void kernel_launch(void* const* d_in, const int* in_sizes, int n_in,
                              void* d_out, int out_size)
{
    const float* x  = (const float*)d_in[0];
    const float* w0 = (const float*)d_in[1];
    const float* b0 = (const float*)d_in[2];
    const float* w1 = (const float*)d_in[3];
    const float* b1 = (const float*)d_in[4];
    const float* w2 = (const float*)d_in[5];
    const float* b2 = (const float*)d_in[6];
    const float* wm = (const float*)d_in[7];
    float* out = (float*)d_out;

    float *F, *H0, *H1, *H2;
    cudaGetSymbolAddress((void**)&F,  g_F);
    cudaGetSymbolAddress((void**)&H0, g_H0);
    cudaGetSymbolAddress((void**)&H1, g_H1);
    cudaGetSymbolAddress((void**)&H2, g_H2);

    // SMEM: ctrl 1024 + 2 stages * (32768 + 2*NT*128)
    constexpr int S0 = 1024 + 2 * (32768 + 2 * 256 * 128);  // 197632 (NT=256)
    constexpr int S1 = 1024 + 2 * (32768 + 2 * 192 * 128);  // 164864 (NT=192)
    constexpr int S2 = 1024 + 2 * (32768 + 2 * 256 * 128);  // 197632 (NT=256)
    cudaFuncSetAttribute(gemm_tc_kernel<256, 512, 588>, cudaFuncAttributeMaxDynamicSharedMemorySize, S0);
    cudaFuncSetAttribute(gemm_tc_kernel<192, 384, 512>, cudaFuncAttributeMaxDynamicSharedMemorySize, S1);
    cudaFuncSetAttribute(gemm_tc_kernel<256, 256, 384>, cudaFuncAttributeMaxDynamicSharedMemorySize, S2);

    featgen_kernel<<<M_TOTAL, 224>>>(x);

    // grid.x = n-tiles (fast; co-resident CTAs share A via L2), grid.y = m-tiles
    gemm_tc_kernel<256, 512, 588><<<dim3(2, M_TOTAL / 128), 512, S0>>>(F,  w0, b0, H0);
    gemm_tc_kernel<192, 384, 512><<<dim3(2, M_TOTAL / 128), 512, S1>>>(H0, w1, b1, H1);
    gemm_tc_kernel<256, 256, 384><<<dim3(1, M_TOTAL / 128), 512, S2>>>(H1, w2, b2, H2);

    reduce_kernel<<<1024, 256>>>(wm, out);
}